// round 10
// baseline (speedup 1.0000x reference)
#include <cuda_runtime.h>
#include <cuda_fp16.h>
#include <cuda_bf16.h>

#define NN 30000
#define NE 240000
#define D1 512
#define D2 128
#define H 2
#define C1 256
#define C2 64
#define NCLS 20
#define EPS 1e-5f
#define NEG 0.2f

// ---------------- scratch ----------------
__device__ half g_xlh1[(size_t)NN * D1];
__device__ float g_xr1[(size_t)NN * D1];
__device__ half g_xlh2[(size_t)NN * D2];
__device__ float g_xr2[(size_t)NN * D2];
__device__ float g_acc1[(size_t)NN * D1];
__device__ float g_acc2[(size_t)NN * D2];
__device__ int g_deg[NN];
__device__ int g_off[NN + 1];
__device__ int g_cursor[NN];
__device__ int g_srcs[NE];
__device__ float g_eas[NE];

// ---------------- CSR build ----------------
__global__ void zero_deg_k(int* deg) {
    int i = blockIdx.x * blockDim.x + threadIdx.x;
    if (i < NN) deg[i] = 0;
}
__global__ void hist_k(const int* __restrict__ dst, int* __restrict__ deg) {
    int e = blockIdx.x * blockDim.x + threadIdx.x;
    if (e < NE) atomicAdd(&deg[dst[e]], 1);
}
__global__ __launch_bounds__(1024) void scan_k(const int* __restrict__ deg,
                                               int* __restrict__ off, int* __restrict__ cursor) {
    __shared__ int partial[1024];
    int t = threadIdx.x;
    const int CH = (NN + 1023) / 1024;
    int base = t * CH;
    int s = 0;
    for (int i = 0; i < CH; i++) {
        int idx = base + i;
        if (idx < NN) s += deg[idx];
    }
    partial[t] = s;
    __syncthreads();
    for (int o = 1; o < 1024; o <<= 1) {
        int v = (t >= o) ? partial[t - o] : 0;
        __syncthreads();
        partial[t] += v;
        __syncthreads();
    }
    int run = (t == 0) ? 0 : partial[t - 1];
    for (int i = 0; i < CH; i++) {
        int idx = base + i;
        if (idx < NN) {
            off[idx] = run;
            cursor[idx] = run;
            run += deg[idx];
        }
    }
    if (t == 1023) off[NN] = partial[1023];
}
__global__ void scatter_k(const int* __restrict__ src, const int* __restrict__ dst,
                          const float* __restrict__ eattr, int* __restrict__ cursor,
                          int* __restrict__ srcs, float* __restrict__ eas) {
    int e = blockIdx.x * blockDim.x + threadIdx.x;
    if (e < NE) {
        int pos = atomicAdd(&cursor[dst[e]], 1);
        srcs[pos] = src[e];
        eas[pos] = eattr[e];
    }
}

// ---------------- fp16 MMA + ldmatrix ----------------
__device__ __forceinline__ void mma_f16(float* c, const unsigned* a, const unsigned* b) {
    asm volatile(
        "mma.sync.aligned.m16n8k16.row.col.f32.f16.f16.f32 "
        "{%0,%1,%2,%3}, {%4,%5,%6,%7}, {%8,%9}, {%0,%1,%2,%3};\n"
        : "+f"(c[0]), "+f"(c[1]), "+f"(c[2]), "+f"(c[3])
        : "r"(a[0]), "r"(a[1]), "r"(a[2]), "r"(a[3]), "r"(b[0]), "r"(b[1]));
}
__device__ __forceinline__ void ldsm_x4(unsigned& r0, unsigned& r1, unsigned& r2, unsigned& r3,
                                        unsigned addr) {
    asm volatile("ldmatrix.sync.aligned.m8n8.x4.shared.b16 {%0,%1,%2,%3}, [%4];"
                 : "=r"(r0), "=r"(r1), "=r"(r2), "=r"(r3)
                 : "r"(addr));
}
__device__ __forceinline__ unsigned pack_h2(float f0, float f1) {
    __half2 h = __floats2half2_rn(f0, f1);
    return *(unsigned*)&h;
}

// ---------------- dual-B fp16 TC GEMM, 128x64 block, 32x32 warp tile, DB + LDSM ----------------
__global__ __launch_bounds__(256) void gemm_f16_k(
    const float* __restrict__ A,
    const float* __restrict__ B0, const float* __restrict__ B1,
    const float* __restrict__ bias0, const float* __restrict__ bias1,
    half* __restrict__ Cl, float* __restrict__ Cr, int M, int Nhalf, int K) {
    __shared__ unsigned As[2][128][12];
    __shared__ unsigned Bs[2][64][12];

    const int tid = threadIdx.x;
    const int lane = tid & 31;
    const int warp = tid >> 5;
    const int wm = warp >> 1;
    const int wn = warp & 1;
    const int groupID = lane >> 2;
    const int tg = lane & 3;
    const int grp = lane >> 3;   // ldmatrix group 0..3
    const int rin = lane & 7;

    const int bm = blockIdx.y * 128;
    const int bn = blockIdx.x * 64;

    const int am0 = tid >> 2;
    const int am1 = am0 + 64;
    const int ak4 = (tid & 3) * 4;
    const int pc = (tid & 3) * 2;
    int agr0 = bm + am0; if (agr0 >= M) agr0 = M - 1;
    int agr1 = bm + am1; if (agr1 >= M) agr1 = M - 1;
    const int gn = bn + am0;
    const float* Bp = (gn < Nhalf) ? B0 : B1;
    const int bcol = (gn < Nhalf) ? gn : gn - Nhalf;

    // ldmatrix lane offsets (u32 units, within one buffer)
    // A tile mt: rows wm*32+mt*16 + (grp&1)*8 + rin, col (grp>>1)*4
    unsigned aoffs[2], boffs[2];
#pragma unroll
    for (int mt = 0; mt < 2; mt++)
        aoffs[mt] = (unsigned)((wm * 32 + mt * 16 + (grp & 1) * 8 + rin) * 12 + (grp >> 1) * 4);
    // B nt-pair p: rows wn*32+p*16 + (grp>>1)*8 + rin, col (grp&1)*4
#pragma unroll
    for (int p = 0; p < 2; p++)
        boffs[p] = (unsigned)((wn * 32 + p * 16 + (grp >> 1) * 8 + rin) * 12 + (grp & 1) * 4);

    unsigned asbase = (unsigned)__cvta_generic_to_shared(&As[0][0][0]);
    unsigned bsbase = (unsigned)__cvta_generic_to_shared(&Bs[0][0][0]);
    const unsigned ABUF = 128 * 12 * 4;  // bytes per A buffer
    const unsigned BBUF = 64 * 12 * 4;

    float4 aReg0 = *(const float4*)&A[(size_t)agr0 * K + ak4];
    float4 aReg1 = *(const float4*)&A[(size_t)agr1 * K + ak4];
    float4 bReg = *(const float4*)&Bp[(size_t)bcol * K + ak4];

    {
        uint2 v;
        v.x = pack_h2(aReg0.x, aReg0.y); v.y = pack_h2(aReg0.z, aReg0.w);
        *(uint2*)&As[0][am0][pc] = v;
        v.x = pack_h2(aReg1.x, aReg1.y); v.y = pack_h2(aReg1.z, aReg1.w);
        *(uint2*)&As[0][am1][pc] = v;
        v.x = pack_h2(bReg.x, bReg.y); v.y = pack_h2(bReg.z, bReg.w);
        *(uint2*)&Bs[0][am0][pc] = v;
    }

    float acc[2][4][4] = {};
    int buf = 0;

    for (int k0 = 0; k0 < K; k0 += 16) {
        __syncthreads();
        bool more = (k0 + 16) < K;
        if (more) {
            aReg0 = *(const float4*)&A[(size_t)agr0 * K + k0 + 16 + ak4];
            aReg1 = *(const float4*)&A[(size_t)agr1 * K + k0 + 16 + ak4];
            bReg = *(const float4*)&Bp[(size_t)bcol * K + k0 + 16 + ak4];
        }

        unsigned ah[2][4], bh[4][2];
        unsigned abb = asbase + buf * ABUF;
        unsigned bbb = bsbase + buf * BBUF;
#pragma unroll
        for (int mt = 0; mt < 2; mt++)
            ldsm_x4(ah[mt][0], ah[mt][1], ah[mt][2], ah[mt][3], abb + aoffs[mt] * 4);
#pragma unroll
        for (int p = 0; p < 2; p++)
            ldsm_x4(bh[2 * p][0], bh[2 * p][1], bh[2 * p + 1][0], bh[2 * p + 1][1],
                    bbb + boffs[p] * 4);

#pragma unroll
        for (int mt = 0; mt < 2; mt++)
#pragma unroll
            for (int nt = 0; nt < 4; nt++)
                mma_f16(acc[mt][nt], ah[mt], bh[nt]);

        if (more) {
            int nb = buf ^ 1;
            uint2 v;
            v.x = pack_h2(aReg0.x, aReg0.y); v.y = pack_h2(aReg0.z, aReg0.w);
            *(uint2*)&As[nb][am0][pc] = v;
            v.x = pack_h2(aReg1.x, aReg1.y); v.y = pack_h2(aReg1.z, aReg1.w);
            *(uint2*)&As[nb][am1][pc] = v;
            v.x = pack_h2(bReg.x, bReg.y); v.y = pack_h2(bReg.z, bReg.w);
            *(uint2*)&Bs[nb][am0][pc] = v;
        }
        buf ^= 1;
    }

#pragma unroll
    for (int mt = 0; mt < 2; mt++) {
        int row0 = bm + wm * 32 + mt * 16 + groupID;
#pragma unroll
        for (int nt = 0; nt < 4; nt++) {
            int col0 = bn + wn * 32 + nt * 8 + tg * 2;
            if (col0 < Nhalf) {
                float b0 = bias0[col0], b1 = bias0[col0 + 1];
                if (row0 < M)
                    *(__half2*)&Cl[(size_t)row0 * Nhalf + col0] =
                        __floats2half2_rn(acc[mt][nt][0] + b0, acc[mt][nt][1] + b1);
                if (row0 + 8 < M)
                    *(__half2*)&Cl[(size_t)(row0 + 8) * Nhalf + col0] =
                        __floats2half2_rn(acc[mt][nt][2] + b0, acc[mt][nt][3] + b1);
            } else {
                int cc = col0 - Nhalf;
                float b0 = bias1[cc], b1 = bias1[cc + 1];
                if (row0 < M) {
                    Cr[(size_t)row0 * Nhalf + cc] = acc[mt][nt][0] + b0;
                    Cr[(size_t)row0 * Nhalf + cc + 1] = acc[mt][nt][1] + b1;
                }
                if (row0 + 8 < M) {
                    Cr[(size_t)(row0 + 8) * Nhalf + cc] = acc[mt][nt][2] + b0;
                    Cr[(size_t)(row0 + 8) * Nhalf + cc + 1] = acc[mt][nt][3] + b1;
                }
            }
        }
    }
}

// ---------------- CSR edge pass, layer 1 (C=256): warp per (dst, head), fp16 gather ----------------
__global__ __launch_bounds__(256) void gat_edge1_k(
    const int* __restrict__ srcs, const float* __restrict__ eas,
    const int* __restrict__ off,
    const half* __restrict__ xlh, const float* __restrict__ xr,
    const float* __restrict__ We, const float* __restrict__ att,
    float* __restrict__ outv) {
    int gw = (blockIdx.x * 256 + threadIdx.x) >> 5;
    int lane = threadIdx.x & 31;
    if (gw >= NN * H) return;
    int h = gw & 1;
    int d = gw >> 1;
    const int cb = h * C1 + lane * 8;

    const float* xrd = xr + (size_t)d * D1 + cb;
    float4 xr_a = *(const float4*)&xrd[0];
    float4 xr_b = *(const float4*)&xrd[4];
    float4 w_a = *(const float4*)&We[cb];
    float4 w_b = *(const float4*)&We[cb + 4];
    float4 t_a = *(const float4*)&att[cb];
    float4 t_b = *(const float4*)&att[cb + 4];

    float4 acc_a = {0, 0, 0, 0}, acc_b = {0, 0, 0, 0};
    float denom = 0.f;
    int i0 = off[d], i1 = off[d + 1];
    int degn = i1 - i0;

    float easum, eac;
    int sc;
    if (degn > 0) {
        sc = srcs[i0];
        eac = eas[i0];
        easum = eac;
    } else {
        sc = d;
        eac = 0.f;
        easum = 0.f;
    }
    uint4 raw = *(const uint4*)&xlh[(size_t)sc * D1 + cb];

    for (int i = i0; i <= i1; i++) {
        uint4 nraw;
        float ean = 0.f;
        if (i < i1) {
            int sn;
            if (i + 1 < i1) {
                sn = srcs[i + 1];
                ean = eas[i + 1];
                easum += ean;
            } else {
                sn = d;
                ean = easum / (float)degn;
            }
            nraw = *(const uint4*)&xlh[(size_t)sn * D1 + cb];
        }
        const __half2* hp = (const __half2*)&raw;
        float2 f0 = __half22float2(hp[0]);
        float2 f1 = __half22float2(hp[1]);
        float2 f2 = __half22float2(hp[2]);
        float2 f3 = __half22float2(hp[3]);
        float v, lg = 0.f;
        v = f0.x + xr_a.x + eac * w_a.x; v = v > 0.f ? v : NEG * v; lg += v * t_a.x;
        v = f0.y + xr_a.y + eac * w_a.y; v = v > 0.f ? v : NEG * v; lg += v * t_a.y;
        v = f1.x + xr_a.z + eac * w_a.z; v = v > 0.f ? v : NEG * v; lg += v * t_a.z;
        v = f1.y + xr_a.w + eac * w_a.w; v = v > 0.f ? v : NEG * v; lg += v * t_a.w;
        v = f2.x + xr_b.x + eac * w_b.x; v = v > 0.f ? v : NEG * v; lg += v * t_b.x;
        v = f2.y + xr_b.y + eac * w_b.y; v = v > 0.f ? v : NEG * v; lg += v * t_b.y;
        v = f3.x + xr_b.z + eac * w_b.z; v = v > 0.f ? v : NEG * v; lg += v * t_b.z;
        v = f3.y + xr_b.w + eac * w_b.w; v = v > 0.f ? v : NEG * v; lg += v * t_b.w;
#pragma unroll
        for (int o = 16; o > 0; o >>= 1) lg += __shfl_xor_sync(0xffffffffu, lg, o);
        float p = __expf(lg);
        denom += p;
        acc_a.x += p * f0.x; acc_a.y += p * f0.y; acc_a.z += p * f1.x; acc_a.w += p * f1.y;
        acc_b.x += p * f2.x; acc_b.y += p * f2.y; acc_b.z += p * f3.x; acc_b.w += p * f3.y;
        if (i < i1) {
            raw = nraw;
            eac = ean;
        }
    }
    float inv = 1.f / denom;
    float* od = outv + (size_t)d * D1 + cb;
    float4 o_a = {acc_a.x * inv, acc_a.y * inv, acc_a.z * inv, acc_a.w * inv};
    float4 o_b = {acc_b.x * inv, acc_b.y * inv, acc_b.z * inv, acc_b.w * inv};
    *(float4*)&od[0] = o_a;
    *(float4*)&od[4] = o_b;
}

// ---------------- CSR edge pass, layer 2 (C=64): warp per dst, fp16 gather ----------------
__global__ __launch_bounds__(256) void gat_edge2_k(
    const int* __restrict__ srcs, const float* __restrict__ eas,
    const int* __restrict__ off,
    const half* __restrict__ xlh, const float* __restrict__ xr,
    const float* __restrict__ We, const float* __restrict__ att,
    float* __restrict__ outv) {
    int gw = (blockIdx.x * 256 + threadIdx.x) >> 5;
    int lane = threadIdx.x & 31;
    if (gw >= NN) return;
    int d = gw;
    int h = lane >> 4;
    int cl = (lane & 15) * 4;
    int gc = h * C2 + cl;

    float4 xr_v = *(const float4*)&xr[(size_t)d * D2 + gc];
    float4 w_v = *(const float4*)&We[gc];
    float4 t_v = *(const float4*)&att[gc];

    float4 acc = {0, 0, 0, 0};
    float denom = 0.f;
    int i0 = off[d], i1 = off[d + 1];
    int degn = i1 - i0;

    float easum, eac;
    int sc;
    if (degn > 0) {
        sc = srcs[i0];
        eac = eas[i0];
        easum = eac;
    } else {
        sc = d;
        eac = 0.f;
        easum = 0.f;
    }
    uint2 raw = *(const uint2*)&xlh[(size_t)sc * D2 + gc];

    for (int i = i0; i <= i1; i++) {
        uint2 nraw;
        float ean = 0.f;
        if (i < i1) {
            int sn;
            if (i + 1 < i1) {
                sn = srcs[i + 1];
                ean = eas[i + 1];
                easum += ean;
            } else {
                sn = d;
                ean = easum / (float)degn;
            }
            nraw = *(const uint2*)&xlh[(size_t)sn * D2 + gc];
        }
        const __half2* hp = (const __half2*)&raw;
        float2 f0 = __half22float2(hp[0]);
        float2 f1 = __half22float2(hp[1]);
        float v, lg = 0.f;
        v = f0.x + xr_v.x + eac * w_v.x; v = v > 0.f ? v : NEG * v; lg += v * t_v.x;
        v = f0.y + xr_v.y + eac * w_v.y; v = v > 0.f ? v : NEG * v; lg += v * t_v.y;
        v = f1.x + xr_v.z + eac * w_v.z; v = v > 0.f ? v : NEG * v; lg += v * t_v.z;
        v = f1.y + xr_v.w + eac * w_v.w; v = v > 0.f ? v : NEG * v; lg += v * t_v.w;
#pragma unroll
        for (int o = 8; o > 0; o >>= 1) lg += __shfl_xor_sync(0xffffffffu, lg, o);
        float p = __expf(lg);
        denom += p;
        acc.x += p * f0.x; acc.y += p * f0.y; acc.z += p * f1.x; acc.w += p * f1.y;
        if (i < i1) {
            raw = nraw;
            eac = ean;
        }
    }
    float inv = 1.f / denom;
    float* od = outv + (size_t)d * D2 + gc;
    float4 o = {acc.x * inv, acc.y * inv, acc.z * inv, acc.w * inv};
    *(float4*)&od[0] = o;
}

// ---------------- bias + (silu) + rmsnorm ----------------
__global__ void postact_rms_k(const float* __restrict__ acc, const float* __restrict__ bias,
                              const float* __restrict__ w, float* __restrict__ out,
                              int D, int do_silu) {
    int n = blockIdx.x;
    float vals[2];
    float ss = 0.f;
    int nv = 0;
    for (int j = threadIdx.x; j < D; j += blockDim.x) {
        float v = acc[(size_t)n * D + j] + bias[j];
        if (do_silu) v = v / (1.f + __expf(-v));
        vals[nv++] = v;
        ss += v * v;
    }
    __shared__ float red[32];
    int lane = threadIdx.x & 31, wid = threadIdx.x >> 5;
#pragma unroll
    for (int o = 16; o > 0; o >>= 1) ss += __shfl_down_sync(0xffffffffu, ss, o);
    if (lane == 0) red[wid] = ss;
    __syncthreads();
    if (wid == 0) {
        float s2 = (lane < (blockDim.x >> 5)) ? red[lane] : 0.f;
#pragma unroll
        for (int o = 16; o > 0; o >>= 1) s2 += __shfl_down_sync(0xffffffffu, s2, o);
        if (lane == 0) red[0] = s2;
    }
    __syncthreads();
    float inv = rsqrtf(red[0] / (float)D + EPS);
    nv = 0;
    for (int j = threadIdx.x; j < D; j += blockDim.x)
        out[(size_t)n * D + j] = vals[nv++] * inv * w[j];
}

// ---------------- classifier ----------------
__global__ void out_gemm_k(const float* __restrict__ h, const float* __restrict__ W,
                           float* __restrict__ out, int N, int K, int Cn) {
    extern __shared__ float Ws[];
    for (int i = threadIdx.x; i < Cn * K; i += blockDim.x) Ws[i] = W[i];
    __syncthreads();
    int idx = blockIdx.x * blockDim.x + threadIdx.x;
    if (idx >= N * Cn) return;
    int n = idx / Cn, c = idx % Cn;
    const float* hr = h + (size_t)n * K;
    const float* wr = Ws + c * K;
    float s = 0.f;
#pragma unroll 8
    for (int k = 0; k < K; k++) s += hr[k] * wr[k];
    out[idx] = s;
}

// ---------------- launch ----------------
static void* sym(const void* s) {
    void* p = nullptr;
    cudaGetSymbolAddress(&p, s);
    return p;
}

extern "C" void kernel_launch(void* const* d_in, const int* in_sizes, int n_in,
                              void* d_out, int out_size) {
    const float* x     = (const float*)d_in[0];
    const int*   ei    = (const int*)d_in[1];
    const float* eattr = (const float*)d_in[2];
    const float* Wl1   = (const float*)d_in[3];
    const float* bl1   = (const float*)d_in[4];
    const float* Wr1   = (const float*)d_in[5];
    const float* br1   = (const float*)d_in[6];
    const float* We1   = (const float*)d_in[7];
    const float* att1  = (const float*)d_in[8];
    const float* bias1 = (const float*)d_in[9];
    const float* Wl2   = (const float*)d_in[10];
    const float* bl2   = (const float*)d_in[11];
    const float* Wr2   = (const float*)d_in[12];
    const float* br2   = (const float*)d_in[13];
    const float* We2   = (const float*)d_in[14];
    const float* att2  = (const float*)d_in[15];
    const float* bias2 = (const float*)d_in[16];
    const float* w_ln1 = (const float*)d_in[17];
    const float* w_ln3 = (const float*)d_in[18];
    const float* W_out = (const float*)d_in[19];
    float* out = (float*)d_out;

    const int* srcp = ei;
    const int* dstp = ei + NE;

    half* xlh1  = (half*)sym(g_xlh1);
    float* xr1  = (float*)sym(g_xr1);
    half* xlh2  = (half*)sym(g_xlh2);
    float* xr2  = (float*)sym(g_xr2);
    float* acc1 = (float*)sym(g_acc1);
    float* acc2 = (float*)sym(g_acc2);
    int* deg    = (int*)sym(g_deg);
    int* off    = (int*)sym(g_off);
    int* cursor = (int*)sym(g_cursor);
    int* srcs   = (int*)sym(g_srcs);
    float* eas  = (float*)sym(g_eas);

    // 0-2: CSR histogram + scan
    zero_deg_k<<<(NN + 255) / 256, 256>>>(deg);
    hist_k<<<(NE + 255) / 256, 256>>>(dstp, deg);
    scan_k<<<1, 1024>>>(deg, off, cursor);

    // 3: layer 1 fused transforms (profiler capture slot)
    dim3 g1(2 * D1 / 64, (NN + 127) / 128);
    gemm_f16_k<<<g1, 256>>>(x, Wl1, Wr1, bl1, br1, xlh1, xr1, NN, D1, D2);

    // 4: permute edges into CSR order
    scatter_k<<<(NE + 255) / 256, 256>>>(srcp, dstp, eattr, cursor, srcs, eas);

    // 5: CSR edge pass layer 1
    gat_edge1_k<<<(NN * H * 32 + 255) / 256, 256>>>(srcs, eas, off, xlh1, xr1, We1, att1, acc1);

    // 6: silu + rmsnorm
    postact_rms_k<<<NN, 256>>>(acc1, bias1, w_ln1, acc1, D1, 1);

    // 7: layer 2 fused transforms
    dim3 g2(2 * D2 / 64, (NN + 127) / 128);
    gemm_f16_k<<<g2, 256>>>(acc1, Wl2, Wr2, bl2, br2, xlh2, xr2, NN, D2, D1);

    // 8: CSR edge pass layer 2
    gat_edge2_k<<<(NN * 32 + 255) / 256, 256>>>(srcs, eas, off, xlh2, xr2, We2, att2, acc2);

    // 9: rmsnorm
    postact_rms_k<<<NN, 256>>>(acc2, bias2, w_ln3, acc2, D2, 0);

    // 10: classifier
    int ntot = NN * NCLS;
    out_gemm_k<<<(ntot + 255) / 256, 256, NCLS * D2 * sizeof(float)>>>(acc2, W_out, out, NN, D2, NCLS);
}

// round 11
// speedup vs baseline: 1.3968x; 1.3968x over previous
#include <cuda_runtime.h>
#include <cuda_fp16.h>
#include <cuda_bf16.h>

#define NN 30000
#define NE 240000
#define D1 512
#define D2 128
#define H 2
#define C1 256
#define C2 64
#define NCLS 20
#define EPS 1e-5f
#define NEG 0.2f

// ---------------- scratch ----------------
__device__ half g_xlh1[(size_t)NN * D1];
__device__ float g_xr1[(size_t)NN * D1];
__device__ half g_xlh2[(size_t)NN * D2];
__device__ float g_xr2[(size_t)NN * D2];
__device__ float g_acc1[(size_t)NN * D1];
__device__ float g_acc2[(size_t)NN * D2];
__device__ int g_deg[NN];
__device__ int g_off[NN + 1];
__device__ int g_cursor[NN];
__device__ int g_srcs[NE];
__device__ float g_eas[NE];

// ---------------- CSR build ----------------
__global__ void zero_deg_k(int* deg) {
    int i = blockIdx.x * blockDim.x + threadIdx.x;
    if (i < NN) deg[i] = 0;
}
__global__ void hist_k(const int* __restrict__ dst, int* __restrict__ deg) {
    int e = blockIdx.x * blockDim.x + threadIdx.x;
    if (e < NE) atomicAdd(&deg[dst[e]], 1);
}
__global__ __launch_bounds__(1024) void scan_k(const int* __restrict__ deg,
                                               int* __restrict__ off, int* __restrict__ cursor) {
    __shared__ int partial[1024];
    int t = threadIdx.x;
    const int CH = (NN + 1023) / 1024;
    int base = t * CH;
    int s = 0;
    for (int i = 0; i < CH; i++) {
        int idx = base + i;
        if (idx < NN) s += deg[idx];
    }
    partial[t] = s;
    __syncthreads();
    for (int o = 1; o < 1024; o <<= 1) {
        int v = (t >= o) ? partial[t - o] : 0;
        __syncthreads();
        partial[t] += v;
        __syncthreads();
    }
    int run = (t == 0) ? 0 : partial[t - 1];
    for (int i = 0; i < CH; i++) {
        int idx = base + i;
        if (idx < NN) {
            off[idx] = run;
            cursor[idx] = run;
            run += deg[idx];
        }
    }
    if (t == 1023) off[NN] = partial[1023];
}
__global__ void scatter_k(const int* __restrict__ src, const int* __restrict__ dst,
                          const float* __restrict__ eattr, int* __restrict__ cursor,
                          int* __restrict__ srcs, float* __restrict__ eas) {
    int e = blockIdx.x * blockDim.x + threadIdx.x;
    if (e < NE) {
        int pos = atomicAdd(&cursor[dst[e]], 1);
        srcs[pos] = src[e];
        eas[pos] = eattr[e];
    }
}

// ---------------- fp16 MMA ----------------
__device__ __forceinline__ void mma_f16(float* c, const unsigned* a, const unsigned* b) {
    asm volatile(
        "mma.sync.aligned.m16n8k16.row.col.f32.f16.f16.f32 "
        "{%0,%1,%2,%3}, {%4,%5,%6,%7}, {%8,%9}, {%0,%1,%2,%3};\n"
        : "+f"(c[0]), "+f"(c[1]), "+f"(c[2]), "+f"(c[3])
        : "r"(a[0]), "r"(a[1]), "r"(a[2]), "r"(a[3]), "r"(b[0]), "r"(b[1]));
}
__device__ __forceinline__ unsigned pack_h2(float f0, float f1) {
    __half2 h = __floats2half2_rn(f0, f1);
    return *(unsigned*)&h;
}

// ---------------- dual-B fp16 TC GEMM, 128x64 block, 32x32 warp tile, double buffer ----------------
__global__ __launch_bounds__(256) void gemm_f16_k(
    const float* __restrict__ A,
    const float* __restrict__ B0, const float* __restrict__ B1,
    const float* __restrict__ bias0, const float* __restrict__ bias1,
    half* __restrict__ Cl, float* __restrict__ Cr, int M, int Nhalf, int K) {
    __shared__ unsigned As[2][128][12];
    __shared__ unsigned Bs[2][64][12];

    const int tid = threadIdx.x;
    const int lane = tid & 31;
    const int warp = tid >> 5;
    const int wm = warp >> 1;
    const int wn = warp & 1;
    const int groupID = lane >> 2;
    const int tg = lane & 3;

    const int bm = blockIdx.y * 128;
    const int bn = blockIdx.x * 64;

    const int am0 = tid >> 2;
    const int am1 = am0 + 64;
    const int ak4 = (tid & 3) * 4;
    const int pc = (tid & 3) * 2;
    int agr0 = bm + am0; if (agr0 >= M) agr0 = M - 1;
    int agr1 = bm + am1; if (agr1 >= M) agr1 = M - 1;
    const int gn = bn + am0;
    const float* Bp = (gn < Nhalf) ? B0 : B1;
    const int bcol = (gn < Nhalf) ? gn : gn - Nhalf;

    float4 aReg0 = *(const float4*)&A[(size_t)agr0 * K + ak4];
    float4 aReg1 = *(const float4*)&A[(size_t)agr1 * K + ak4];
    float4 bReg = *(const float4*)&Bp[(size_t)bcol * K + ak4];

    As[0][am0][pc] = pack_h2(aReg0.x, aReg0.y);
    As[0][am0][pc + 1] = pack_h2(aReg0.z, aReg0.w);
    As[0][am1][pc] = pack_h2(aReg1.x, aReg1.y);
    As[0][am1][pc + 1] = pack_h2(aReg1.z, aReg1.w);
    Bs[0][am0][pc] = pack_h2(bReg.x, bReg.y);
    Bs[0][am0][pc + 1] = pack_h2(bReg.z, bReg.w);

    float acc[2][4][4] = {};
    int buf = 0;

    for (int k0 = 0; k0 < K; k0 += 16) {
        __syncthreads();
        bool more = (k0 + 16) < K;
        if (more) {
            aReg0 = *(const float4*)&A[(size_t)agr0 * K + k0 + 16 + ak4];
            aReg1 = *(const float4*)&A[(size_t)agr1 * K + k0 + 16 + ak4];
            bReg = *(const float4*)&Bp[(size_t)bcol * K + k0 + 16 + ak4];
        }

        unsigned ah[2][4], bh[4][2];
#pragma unroll
        for (int mt = 0; mt < 2; mt++) {
            int r = wm * 32 + mt * 16 + groupID;
            ah[mt][0] = As[buf][r][tg];
            ah[mt][1] = As[buf][r + 8][tg];
            ah[mt][2] = As[buf][r][tg + 4];
            ah[mt][3] = As[buf][r + 8][tg + 4];
        }
#pragma unroll
        for (int nt = 0; nt < 4; nt++) {
            int n = wn * 32 + nt * 8 + groupID;
            bh[nt][0] = Bs[buf][n][tg];
            bh[nt][1] = Bs[buf][n][tg + 4];
        }
#pragma unroll
        for (int mt = 0; mt < 2; mt++)
#pragma unroll
            for (int nt = 0; nt < 4; nt++)
                mma_f16(acc[mt][nt], ah[mt], bh[nt]);

        if (more) {
            int nb = buf ^ 1;
            As[nb][am0][pc] = pack_h2(aReg0.x, aReg0.y);
            As[nb][am0][pc + 1] = pack_h2(aReg0.z, aReg0.w);
            As[nb][am1][pc] = pack_h2(aReg1.x, aReg1.y);
            As[nb][am1][pc + 1] = pack_h2(aReg1.z, aReg1.w);
            Bs[nb][am0][pc] = pack_h2(bReg.x, bReg.y);
            Bs[nb][am0][pc + 1] = pack_h2(bReg.z, bReg.w);
        }
        buf ^= 1;
    }

#pragma unroll
    for (int mt = 0; mt < 2; mt++) {
        int row0 = bm + wm * 32 + mt * 16 + groupID;
#pragma unroll
        for (int nt = 0; nt < 4; nt++) {
            int col0 = bn + wn * 32 + nt * 8 + tg * 2;
            if (col0 < Nhalf) {
                float b0 = bias0[col0], b1 = bias0[col0 + 1];
                if (row0 < M)
                    *(__half2*)&Cl[(size_t)row0 * Nhalf + col0] =
                        __floats2half2_rn(acc[mt][nt][0] + b0, acc[mt][nt][1] + b1);
                if (row0 + 8 < M)
                    *(__half2*)&Cl[(size_t)(row0 + 8) * Nhalf + col0] =
                        __floats2half2_rn(acc[mt][nt][2] + b0, acc[mt][nt][3] + b1);
            } else {
                int cc = col0 - Nhalf;
                float b0 = bias1[cc], b1 = bias1[cc + 1];
                if (row0 < M) {
                    Cr[(size_t)row0 * Nhalf + cc] = acc[mt][nt][0] + b0;
                    Cr[(size_t)row0 * Nhalf + cc + 1] = acc[mt][nt][1] + b1;
                }
                if (row0 + 8 < M) {
                    Cr[(size_t)(row0 + 8) * Nhalf + cc] = acc[mt][nt][2] + b0;
                    Cr[(size_t)(row0 + 8) * Nhalf + cc + 1] = acc[mt][nt][3] + b1;
                }
            }
        }
    }
}

// ---------------- CSR edge pass, layer 1 (C=256): warp per (dst, head), fp16 gather ----------------
__global__ __launch_bounds__(256) void gat_edge1_k(
    const int* __restrict__ srcs, const float* __restrict__ eas,
    const int* __restrict__ off,
    const half* __restrict__ xlh, const float* __restrict__ xr,
    const float* __restrict__ We, const float* __restrict__ att,
    float* __restrict__ outv) {
    int gw = (blockIdx.x * 256 + threadIdx.x) >> 5;
    int lane = threadIdx.x & 31;
    if (gw >= NN * H) return;
    int h = gw & 1;
    int d = gw >> 1;
    const int cb = h * C1 + lane * 8;

    const float* xrd = xr + (size_t)d * D1 + cb;
    float4 xr_a = *(const float4*)&xrd[0];
    float4 xr_b = *(const float4*)&xrd[4];
    float4 w_a = *(const float4*)&We[cb];
    float4 w_b = *(const float4*)&We[cb + 4];
    float4 t_a = *(const float4*)&att[cb];
    float4 t_b = *(const float4*)&att[cb + 4];

    float4 acc_a = {0, 0, 0, 0}, acc_b = {0, 0, 0, 0};
    float denom = 0.f;
    int i0 = off[d], i1 = off[d + 1];
    int degn = i1 - i0;

    float easum, eac;
    int sc;
    if (degn > 0) {
        sc = srcs[i0];
        eac = eas[i0];
        easum = eac;
    } else {
        sc = d;
        eac = 0.f;
        easum = 0.f;
    }
    uint4 raw = *(const uint4*)&xlh[(size_t)sc * D1 + cb];

    for (int i = i0; i <= i1; i++) {
        uint4 nraw;
        float ean = 0.f;
        if (i < i1) {
            int sn;
            if (i + 1 < i1) {
                sn = srcs[i + 1];
                ean = eas[i + 1];
                easum += ean;
            } else {
                sn = d;
                ean = easum / (float)degn;
            }
            nraw = *(const uint4*)&xlh[(size_t)sn * D1 + cb];
        }
        const __half2* hp = (const __half2*)&raw;
        float2 f0 = __half22float2(hp[0]);
        float2 f1 = __half22float2(hp[1]);
        float2 f2 = __half22float2(hp[2]);
        float2 f3 = __half22float2(hp[3]);
        float v, lg = 0.f;
        v = f0.x + xr_a.x + eac * w_a.x; v = v > 0.f ? v : NEG * v; lg += v * t_a.x;
        v = f0.y + xr_a.y + eac * w_a.y; v = v > 0.f ? v : NEG * v; lg += v * t_a.y;
        v = f1.x + xr_a.z + eac * w_a.z; v = v > 0.f ? v : NEG * v; lg += v * t_a.z;
        v = f1.y + xr_a.w + eac * w_a.w; v = v > 0.f ? v : NEG * v; lg += v * t_a.w;
        v = f2.x + xr_b.x + eac * w_b.x; v = v > 0.f ? v : NEG * v; lg += v * t_b.x;
        v = f2.y + xr_b.y + eac * w_b.y; v = v > 0.f ? v : NEG * v; lg += v * t_b.y;
        v = f3.x + xr_b.z + eac * w_b.z; v = v > 0.f ? v : NEG * v; lg += v * t_b.z;
        v = f3.y + xr_b.w + eac * w_b.w; v = v > 0.f ? v : NEG * v; lg += v * t_b.w;
#pragma unroll
        for (int o = 16; o > 0; o >>= 1) lg += __shfl_xor_sync(0xffffffffu, lg, o);
        float p = __expf(lg);
        denom += p;
        acc_a.x += p * f0.x; acc_a.y += p * f0.y; acc_a.z += p * f1.x; acc_a.w += p * f1.y;
        acc_b.x += p * f2.x; acc_b.y += p * f2.y; acc_b.z += p * f3.x; acc_b.w += p * f3.y;
        if (i < i1) {
            raw = nraw;
            eac = ean;
        }
    }
    float inv = 1.f / denom;
    float* od = outv + (size_t)d * D1 + cb;
    float4 o_a = {acc_a.x * inv, acc_a.y * inv, acc_a.z * inv, acc_a.w * inv};
    float4 o_b = {acc_b.x * inv, acc_b.y * inv, acc_b.z * inv, acc_b.w * inv};
    *(float4*)&od[0] = o_a;
    *(float4*)&od[4] = o_b;
}

// ---------------- CSR edge pass, layer 2 (C=64): warp per dst, fp16 gather ----------------
__global__ __launch_bounds__(256) void gat_edge2_k(
    const int* __restrict__ srcs, const float* __restrict__ eas,
    const int* __restrict__ off,
    const half* __restrict__ xlh, const float* __restrict__ xr,
    const float* __restrict__ We, const float* __restrict__ att,
    float* __restrict__ outv) {
    int gw = (blockIdx.x * 256 + threadIdx.x) >> 5;
    int lane = threadIdx.x & 31;
    if (gw >= NN) return;
    int d = gw;
    int h = lane >> 4;
    int cl = (lane & 15) * 4;
    int gc = h * C2 + cl;

    float4 xr_v = *(const float4*)&xr[(size_t)d * D2 + gc];
    float4 w_v = *(const float4*)&We[gc];
    float4 t_v = *(const float4*)&att[gc];

    float4 acc = {0, 0, 0, 0};
    float denom = 0.f;
    int i0 = off[d], i1 = off[d + 1];
    int degn = i1 - i0;

    float easum, eac;
    int sc;
    if (degn > 0) {
        sc = srcs[i0];
        eac = eas[i0];
        easum = eac;
    } else {
        sc = d;
        eac = 0.f;
        easum = 0.f;
    }
    uint2 raw = *(const uint2*)&xlh[(size_t)sc * D2 + gc];

    for (int i = i0; i <= i1; i++) {
        uint2 nraw;
        float ean = 0.f;
        if (i < i1) {
            int sn;
            if (i + 1 < i1) {
                sn = srcs[i + 1];
                ean = eas[i + 1];
                easum += ean;
            } else {
                sn = d;
                ean = easum / (float)degn;
            }
            nraw = *(const uint2*)&xlh[(size_t)sn * D2 + gc];
        }
        const __half2* hp = (const __half2*)&raw;
        float2 f0 = __half22float2(hp[0]);
        float2 f1 = __half22float2(hp[1]);
        float v, lg = 0.f;
        v = f0.x + xr_v.x + eac * w_v.x; v = v > 0.f ? v : NEG * v; lg += v * t_v.x;
        v = f0.y + xr_v.y + eac * w_v.y; v = v > 0.f ? v : NEG * v; lg += v * t_v.y;
        v = f1.x + xr_v.z + eac * w_v.z; v = v > 0.f ? v : NEG * v; lg += v * t_v.z;
        v = f1.y + xr_v.w + eac * w_v.w; v = v > 0.f ? v : NEG * v; lg += v * t_v.w;
#pragma unroll
        for (int o = 8; o > 0; o >>= 1) lg += __shfl_xor_sync(0xffffffffu, lg, o);
        float p = __expf(lg);
        denom += p;
        acc.x += p * f0.x; acc.y += p * f0.y; acc.z += p * f1.x; acc.w += p * f1.y;
        if (i < i1) {
            raw = nraw;
            eac = ean;
        }
    }
    float inv = 1.f / denom;
    float* od = outv + (size_t)d * D2 + gc;
    float4 o = {acc.x * inv, acc.y * inv, acc.z * inv, acc.w * inv};
    *(float4*)&od[0] = o;
}

// ---------------- bias + (silu) + rmsnorm ----------------
__global__ void postact_rms_k(const float* __restrict__ acc, const float* __restrict__ bias,
                              const float* __restrict__ w, float* __restrict__ out,
                              int D, int do_silu) {
    int n = blockIdx.x;
    float vals[2];
    float ss = 0.f;
    int nv = 0;
    for (int j = threadIdx.x; j < D; j += blockDim.x) {
        float v = acc[(size_t)n * D + j] + bias[j];
        if (do_silu) v = v / (1.f + __expf(-v));
        vals[nv++] = v;
        ss += v * v;
    }
    __shared__ float red[32];
    int lane = threadIdx.x & 31, wid = threadIdx.x >> 5;
#pragma unroll
    for (int o = 16; o > 0; o >>= 1) ss += __shfl_down_sync(0xffffffffu, ss, o);
    if (lane == 0) red[wid] = ss;
    __syncthreads();
    if (wid == 0) {
        float s2 = (lane < (blockDim.x >> 5)) ? red[lane] : 0.f;
#pragma unroll
        for (int o = 16; o > 0; o >>= 1) s2 += __shfl_down_sync(0xffffffffu, s2, o);
        if (lane == 0) red[0] = s2;
    }
    __syncthreads();
    float inv = rsqrtf(red[0] / (float)D + EPS);
    nv = 0;
    for (int j = threadIdx.x; j < D; j += blockDim.x)
        out[(size_t)n * D + j] = vals[nv++] * inv * w[j];
}

// ---------------- classifier: warp per node, h row read once ----------------
__global__ __launch_bounds__(256) void out_gemm_k(const float* __restrict__ h,
                                                  const float* __restrict__ W,
                                                  float* __restrict__ out) {
    __shared__ float Ws[NCLS * D2];
    for (int i = threadIdx.x; i < NCLS * D2; i += 256) Ws[i] = W[i];
    __syncthreads();
    int warp = threadIdx.x >> 5;
    int lane = threadIdx.x & 31;
    int n = blockIdx.x * 8 + warp;
    if (n >= NN) return;
    // each lane holds 4 h values
    float4 hv = *(const float4*)&h[(size_t)n * D2 + lane * 4];
#pragma unroll
    for (int c = 0; c < NCLS; c++) {
        const float* wr = Ws + c * D2 + lane * 4;
        float s = hv.x * wr[0] + hv.y * wr[1] + hv.z * wr[2] + hv.w * wr[3];
#pragma unroll
        for (int o = 16; o > 0; o >>= 1) s += __shfl_xor_sync(0xffffffffu, s, o);
        if (lane == 0) out[(size_t)n * NCLS + c] = s;
    }
}

// ---------------- launch ----------------
static void* sym(const void* s) {
    void* p = nullptr;
    cudaGetSymbolAddress(&p, s);
    return p;
}

extern "C" void kernel_launch(void* const* d_in, const int* in_sizes, int n_in,
                              void* d_out, int out_size) {
    const float* x     = (const float*)d_in[0];
    const int*   ei    = (const int*)d_in[1];
    const float* eattr = (const float*)d_in[2];
    const float* Wl1   = (const float*)d_in[3];
    const float* bl1   = (const float*)d_in[4];
    const float* Wr1   = (const float*)d_in[5];
    const float* br1   = (const float*)d_in[6];
    const float* We1   = (const float*)d_in[7];
    const float* att1  = (const float*)d_in[8];
    const float* bias1 = (const float*)d_in[9];
    const float* Wl2   = (const float*)d_in[10];
    const float* bl2   = (const float*)d_in[11];
    const float* Wr2   = (const float*)d_in[12];
    const float* br2   = (const float*)d_in[13];
    const float* We2   = (const float*)d_in[14];
    const float* att2  = (const float*)d_in[15];
    const float* bias2 = (const float*)d_in[16];
    const float* w_ln1 = (const float*)d_in[17];
    const float* w_ln3 = (const float*)d_in[18];
    const float* W_out = (const float*)d_in[19];
    float* out = (float*)d_out;

    const int* srcp = ei;
    const int* dstp = ei + NE;

    half* xlh1  = (half*)sym(g_xlh1);
    float* xr1  = (float*)sym(g_xr1);
    half* xlh2  = (half*)sym(g_xlh2);
    float* xr2  = (float*)sym(g_xr2);
    float* acc1 = (float*)sym(g_acc1);
    float* acc2 = (float*)sym(g_acc2);
    int* deg    = (int*)sym(g_deg);
    int* off    = (int*)sym(g_off);
    int* cursor = (int*)sym(g_cursor);
    int* srcs   = (int*)sym(g_srcs);
    float* eas  = (float*)sym(g_eas);

    // 0-2: CSR histogram + scan
    zero_deg_k<<<(NN + 255) / 256, 256>>>(deg);
    hist_k<<<(NE + 255) / 256, 256>>>(dstp, deg);
    scan_k<<<1, 1024>>>(deg, off, cursor);

    // 3: layer 1 fused transforms (profiler capture slot)
    dim3 g1(2 * D1 / 64, (NN + 127) / 128);
    gemm_f16_k<<<g1, 256>>>(x, Wl1, Wr1, bl1, br1, xlh1, xr1, NN, D1, D2);

    // 4: permute edges into CSR order
    scatter_k<<<(NE + 255) / 256, 256>>>(srcp, dstp, eattr, cursor, srcs, eas);

    // 5: CSR edge pass layer 1
    gat_edge1_k<<<(NN * H * 32 + 255) / 256, 256>>>(srcs, eas, off, xlh1, xr1, We1, att1, acc1);

    // 6: silu + rmsnorm
    postact_rms_k<<<NN, 256>>>(acc1, bias1, w_ln1, acc1, D1, 1);

    // 7: layer 2 fused transforms
    dim3 g2(2 * D2 / 64, (NN + 127) / 128);
    gemm_f16_k<<<g2, 256>>>(acc1, Wl2, Wr2, bl2, br2, xlh2, xr2, NN, D2, D1);

    // 8: CSR edge pass layer 2
    gat_edge2_k<<<(NN * 32 + 255) / 256, 256>>>(srcs, eas, off, xlh2, xr2, We2, att2, acc2);

    // 9: rmsnorm (128 threads — D2 = 128)
    postact_rms_k<<<NN, 128>>>(acc2, bias2, w_ln3, acc2, D2, 0);

    // 10: classifier — warp per node
    out_gemm_k<<<(NN + 7) / 8, 256>>>(acc2, W_out, out);
}

// round 12
// speedup vs baseline: 1.4147x; 1.0128x over previous
#include <cuda_runtime.h>
#include <cuda_fp16.h>
#include <cuda_bf16.h>

#define NN 30000
#define NE 240000
#define D1 512
#define D2 128
#define H 2
#define C1 256
#define C2 64
#define NCLS 20
#define EPS 1e-5f
#define NEG 0.2f

// ---------------- scratch ----------------
__device__ half g_xlh1[(size_t)NN * D1];
__device__ float g_xr1[(size_t)NN * D1];
__device__ half g_xlh2[(size_t)NN * D2];
__device__ float g_xr2[(size_t)NN * D2];
__device__ float g_acc1[(size_t)NN * D1];
__device__ float g_acc2[(size_t)NN * D2];
__device__ int g_deg[NN];
__device__ int g_off[NN + 1];
__device__ int g_cursor[NN];
__device__ int g_srcs[NE];
__device__ float g_eas[NE];

// ---------------- CSR build ----------------
__global__ void zero_deg_k(int* deg) {
    int i = blockIdx.x * blockDim.x + threadIdx.x;
    if (i < NN) deg[i] = 0;
}
__global__ void hist_k(const int* __restrict__ dst, int* __restrict__ deg) {
    int e = blockIdx.x * blockDim.x + threadIdx.x;
    if (e < NE) atomicAdd(&deg[dst[e]], 1);
}
__global__ __launch_bounds__(1024) void scan_k(const int* __restrict__ deg,
                                               int* __restrict__ off, int* __restrict__ cursor) {
    __shared__ int partial[1024];
    int t = threadIdx.x;
    const int CH = (NN + 1023) / 1024;
    int base = t * CH;
    int s = 0;
    for (int i = 0; i < CH; i++) {
        int idx = base + i;
        if (idx < NN) s += deg[idx];
    }
    partial[t] = s;
    __syncthreads();
    for (int o = 1; o < 1024; o <<= 1) {
        int v = (t >= o) ? partial[t - o] : 0;
        __syncthreads();
        partial[t] += v;
        __syncthreads();
    }
    int run = (t == 0) ? 0 : partial[t - 1];
    for (int i = 0; i < CH; i++) {
        int idx = base + i;
        if (idx < NN) {
            off[idx] = run;
            cursor[idx] = run;
            run += deg[idx];
        }
    }
    if (t == 1023) off[NN] = partial[1023];
}
__global__ void scatter_k(const int* __restrict__ src, const int* __restrict__ dst,
                          const float* __restrict__ eattr, int* __restrict__ cursor,
                          int* __restrict__ srcs, float* __restrict__ eas) {
    int e = blockIdx.x * blockDim.x + threadIdx.x;
    if (e < NE) {
        int pos = atomicAdd(&cursor[dst[e]], 1);
        srcs[pos] = src[e];
        eas[pos] = eattr[e];
    }
}

// ---------------- fp16 MMA ----------------
__device__ __forceinline__ void mma_f16(float* c, const unsigned* a, const unsigned* b) {
    asm volatile(
        "mma.sync.aligned.m16n8k16.row.col.f32.f16.f16.f32 "
        "{%0,%1,%2,%3}, {%4,%5,%6,%7}, {%8,%9}, {%0,%1,%2,%3};\n"
        : "+f"(c[0]), "+f"(c[1]), "+f"(c[2]), "+f"(c[3])
        : "r"(a[0]), "r"(a[1]), "r"(a[2]), "r"(a[3]), "r"(b[0]), "r"(b[1]));
}
__device__ __forceinline__ unsigned pack_h2(float f0, float f1) {
    __half2 h = __floats2half2_rn(f0, f1);
    return *(unsigned*)&h;
}

// ---------------- dual-B fp16 TC GEMM, 128x64 block, 32x32 warp tile, double buffer ----------------
__global__ __launch_bounds__(256) void gemm_f16_k(
    const float* __restrict__ A,
    const float* __restrict__ B0, const float* __restrict__ B1,
    const float* __restrict__ bias0, const float* __restrict__ bias1,
    half* __restrict__ Cl, float* __restrict__ Cr, int M, int Nhalf, int K) {
    __shared__ unsigned As[2][128][12];
    __shared__ unsigned Bs[2][64][12];

    const int tid = threadIdx.x;
    const int lane = tid & 31;
    const int warp = tid >> 5;
    const int wm = warp >> 1;
    const int wn = warp & 1;
    const int groupID = lane >> 2;
    const int tg = lane & 3;

    const int bm = blockIdx.y * 128;
    const int bn = blockIdx.x * 64;

    const int am0 = tid >> 2;
    const int am1 = am0 + 64;
    const int ak4 = (tid & 3) * 4;
    const int pc = (tid & 3) * 2;
    int agr0 = bm + am0; if (agr0 >= M) agr0 = M - 1;
    int agr1 = bm + am1; if (agr1 >= M) agr1 = M - 1;
    const int gn = bn + am0;
    const float* Bp = (gn < Nhalf) ? B0 : B1;
    const int bcol = (gn < Nhalf) ? gn : gn - Nhalf;

    float4 aReg0 = *(const float4*)&A[(size_t)agr0 * K + ak4];
    float4 aReg1 = *(const float4*)&A[(size_t)agr1 * K + ak4];
    float4 bReg = *(const float4*)&Bp[(size_t)bcol * K + ak4];

    As[0][am0][pc] = pack_h2(aReg0.x, aReg0.y);
    As[0][am0][pc + 1] = pack_h2(aReg0.z, aReg0.w);
    As[0][am1][pc] = pack_h2(aReg1.x, aReg1.y);
    As[0][am1][pc + 1] = pack_h2(aReg1.z, aReg1.w);
    Bs[0][am0][pc] = pack_h2(bReg.x, bReg.y);
    Bs[0][am0][pc + 1] = pack_h2(bReg.z, bReg.w);

    float acc[2][4][4] = {};
    int buf = 0;

    for (int k0 = 0; k0 < K; k0 += 16) {
        __syncthreads();
        bool more = (k0 + 16) < K;
        if (more) {
            aReg0 = *(const float4*)&A[(size_t)agr0 * K + k0 + 16 + ak4];
            aReg1 = *(const float4*)&A[(size_t)agr1 * K + k0 + 16 + ak4];
            bReg = *(const float4*)&Bp[(size_t)bcol * K + k0 + 16 + ak4];
        }

        unsigned ah[2][4], bh[4][2];
#pragma unroll
        for (int mt = 0; mt < 2; mt++) {
            int r = wm * 32 + mt * 16 + groupID;
            ah[mt][0] = As[buf][r][tg];
            ah[mt][1] = As[buf][r + 8][tg];
            ah[mt][2] = As[buf][r][tg + 4];
            ah[mt][3] = As[buf][r + 8][tg + 4];
        }
#pragma unroll
        for (int nt = 0; nt < 4; nt++) {
            int n = wn * 32 + nt * 8 + groupID;
            bh[nt][0] = Bs[buf][n][tg];
            bh[nt][1] = Bs[buf][n][tg + 4];
        }
#pragma unroll
        for (int mt = 0; mt < 2; mt++)
#pragma unroll
            for (int nt = 0; nt < 4; nt++)
                mma_f16(acc[mt][nt], ah[mt], bh[nt]);

        if (more) {
            int nb = buf ^ 1;
            As[nb][am0][pc] = pack_h2(aReg0.x, aReg0.y);
            As[nb][am0][pc + 1] = pack_h2(aReg0.z, aReg0.w);
            As[nb][am1][pc] = pack_h2(aReg1.x, aReg1.y);
            As[nb][am1][pc + 1] = pack_h2(aReg1.z, aReg1.w);
            Bs[nb][am0][pc] = pack_h2(bReg.x, bReg.y);
            Bs[nb][am0][pc + 1] = pack_h2(bReg.z, bReg.w);
        }
        buf ^= 1;
    }

#pragma unroll
    for (int mt = 0; mt < 2; mt++) {
        int row0 = bm + wm * 32 + mt * 16 + groupID;
#pragma unroll
        for (int nt = 0; nt < 4; nt++) {
            int col0 = bn + wn * 32 + nt * 8 + tg * 2;
            if (col0 < Nhalf) {
                float b0 = bias0[col0], b1 = bias0[col0 + 1];
                if (row0 < M)
                    *(__half2*)&Cl[(size_t)row0 * Nhalf + col0] =
                        __floats2half2_rn(acc[mt][nt][0] + b0, acc[mt][nt][1] + b1);
                if (row0 + 8 < M)
                    *(__half2*)&Cl[(size_t)(row0 + 8) * Nhalf + col0] =
                        __floats2half2_rn(acc[mt][nt][2] + b0, acc[mt][nt][3] + b1);
            } else {
                int cc = col0 - Nhalf;
                float b0 = bias1[cc], b1 = bias1[cc + 1];
                if (row0 < M) {
                    Cr[(size_t)row0 * Nhalf + cc] = acc[mt][nt][0] + b0;
                    Cr[(size_t)row0 * Nhalf + cc + 1] = acc[mt][nt][1] + b1;
                }
                if (row0 + 8 < M) {
                    Cr[(size_t)(row0 + 8) * Nhalf + cc] = acc[mt][nt][2] + b0;
                    Cr[(size_t)(row0 + 8) * Nhalf + cc + 1] = acc[mt][nt][3] + b1;
                }
            }
        }
    }
}

// ---------------- CSR edge pass, layer 1 (C=256): warp per (dst, head), prefetch-2 ----------------
__global__ __launch_bounds__(256) void gat_edge1_k(
    const int* __restrict__ srcs, const float* __restrict__ eas,
    const int* __restrict__ off,
    const half* __restrict__ xlh, const float* __restrict__ xr,
    const float* __restrict__ We, const float* __restrict__ att,
    float* __restrict__ outv) {
    int gw = (blockIdx.x * 256 + threadIdx.x) >> 5;
    int lane = threadIdx.x & 31;
    if (gw >= NN * H) return;
    int h = gw & 1;
    int d = gw >> 1;
    const int cb = h * C1 + lane * 8;

    float4 xr_a = __ldcs((const float4*)&xr[(size_t)d * D1 + cb]);
    float4 xr_b = __ldcs((const float4*)&xr[(size_t)d * D1 + cb + 4]);
    float4 w_a = *(const float4*)&We[cb];
    float4 w_b = *(const float4*)&We[cb + 4];
    float4 t_a = *(const float4*)&att[cb];
    float4 t_b = *(const float4*)&att[cb + 4];

    float4 acc_a = {0, 0, 0, 0}, acc_b = {0, 0, 0, 0};
    float denom = 0.f;
    int i0 = off[d], i1 = off[d + 1];
    int degn = i1 - i0;
    float invdeg = 1.f / fmaxf((float)degn, 1.f);
    float easum = 0.f;

    // loader: issues gather for index j (j==i1 => self loop; easum complete by then)
    auto ld = [&](int j, uint4& raw, float& ea) {
        int s;
        if (j < i1) {
            s = srcs[j];
            ea = eas[j];
            easum += ea;
        } else {
            s = d;
            ea = easum * invdeg;
        }
        raw = *(const uint4*)&xlh[(size_t)s * D1 + cb];
    };

    uint4 rawA, rawB, rawC;
    float eaA, eaB, eaC;
    ld(i0, rawA, eaA);
    if (i0 + 1 <= i1) ld(i0 + 1, rawB, eaB);

    for (int i = i0; i <= i1; i++) {
        if (i + 2 <= i1) ld(i + 2, rawC, eaC);
        const __half2* hp = (const __half2*)&rawA;
        float2 f0 = __half22float2(hp[0]);
        float2 f1 = __half22float2(hp[1]);
        float2 f2 = __half22float2(hp[2]);
        float2 f3 = __half22float2(hp[3]);
        float eac = eaA;
        float v, lg = 0.f;
        v = f0.x + xr_a.x + eac * w_a.x; v = v > 0.f ? v : NEG * v; lg += v * t_a.x;
        v = f0.y + xr_a.y + eac * w_a.y; v = v > 0.f ? v : NEG * v; lg += v * t_a.y;
        v = f1.x + xr_a.z + eac * w_a.z; v = v > 0.f ? v : NEG * v; lg += v * t_a.z;
        v = f1.y + xr_a.w + eac * w_a.w; v = v > 0.f ? v : NEG * v; lg += v * t_a.w;
        v = f2.x + xr_b.x + eac * w_b.x; v = v > 0.f ? v : NEG * v; lg += v * t_b.x;
        v = f2.y + xr_b.y + eac * w_b.y; v = v > 0.f ? v : NEG * v; lg += v * t_b.y;
        v = f3.x + xr_b.z + eac * w_b.z; v = v > 0.f ? v : NEG * v; lg += v * t_b.z;
        v = f3.y + xr_b.w + eac * w_b.w; v = v > 0.f ? v : NEG * v; lg += v * t_b.w;
#pragma unroll
        for (int o = 16; o > 0; o >>= 1) lg += __shfl_xor_sync(0xffffffffu, lg, o);
        float p = __expf(lg);
        denom += p;
        acc_a.x += p * f0.x; acc_a.y += p * f0.y; acc_a.z += p * f1.x; acc_a.w += p * f1.y;
        acc_b.x += p * f2.x; acc_b.y += p * f2.y; acc_b.z += p * f3.x; acc_b.w += p * f3.y;
        rawA = rawB; eaA = eaB;
        rawB = rawC; eaB = eaC;
    }
    float inv = 1.f / denom;
    float* od = outv + (size_t)d * D1 + cb;
    float4 o_a = {acc_a.x * inv, acc_a.y * inv, acc_a.z * inv, acc_a.w * inv};
    float4 o_b = {acc_b.x * inv, acc_b.y * inv, acc_b.z * inv, acc_b.w * inv};
    __stcs((float4*)&od[0], o_a);
    __stcs((float4*)&od[4], o_b);
}

// ---------------- CSR edge pass, layer 2 (C=64): warp per dst, prefetch-2 ----------------
__global__ __launch_bounds__(256) void gat_edge2_k(
    const int* __restrict__ srcs, const float* __restrict__ eas,
    const int* __restrict__ off,
    const half* __restrict__ xlh, const float* __restrict__ xr,
    const float* __restrict__ We, const float* __restrict__ att,
    float* __restrict__ outv) {
    int gw = (blockIdx.x * 256 + threadIdx.x) >> 5;
    int lane = threadIdx.x & 31;
    if (gw >= NN) return;
    int d = gw;
    int h = lane >> 4;
    int cl = (lane & 15) * 4;
    int gc = h * C2 + cl;

    float4 xr_v = __ldcs((const float4*)&xr[(size_t)d * D2 + gc]);
    float4 w_v = *(const float4*)&We[gc];
    float4 t_v = *(const float4*)&att[gc];

    float4 acc = {0, 0, 0, 0};
    float denom = 0.f;
    int i0 = off[d], i1 = off[d + 1];
    int degn = i1 - i0;
    float invdeg = 1.f / fmaxf((float)degn, 1.f);
    float easum = 0.f;

    auto ld = [&](int j, uint2& raw, float& ea) {
        int s;
        if (j < i1) {
            s = srcs[j];
            ea = eas[j];
            easum += ea;
        } else {
            s = d;
            ea = easum * invdeg;
        }
        raw = *(const uint2*)&xlh[(size_t)s * D2 + gc];
    };

    uint2 rawA, rawB, rawC;
    float eaA, eaB, eaC;
    ld(i0, rawA, eaA);
    if (i0 + 1 <= i1) ld(i0 + 1, rawB, eaB);

    for (int i = i0; i <= i1; i++) {
        if (i + 2 <= i1) ld(i + 2, rawC, eaC);
        const __half2* hp = (const __half2*)&rawA;
        float2 f0 = __half22float2(hp[0]);
        float2 f1 = __half22float2(hp[1]);
        float eac = eaA;
        float v, lg = 0.f;
        v = f0.x + xr_v.x + eac * w_v.x; v = v > 0.f ? v : NEG * v; lg += v * t_v.x;
        v = f0.y + xr_v.y + eac * w_v.y; v = v > 0.f ? v : NEG * v; lg += v * t_v.y;
        v = f1.x + xr_v.z + eac * w_v.z; v = v > 0.f ? v : NEG * v; lg += v * t_v.z;
        v = f1.y + xr_v.w + eac * w_v.w; v = v > 0.f ? v : NEG * v; lg += v * t_v.w;
#pragma unroll
        for (int o = 8; o > 0; o >>= 1) lg += __shfl_xor_sync(0xffffffffu, lg, o);
        float p = __expf(lg);
        denom += p;
        acc.x += p * f0.x; acc.y += p * f0.y; acc.z += p * f1.x; acc.w += p * f1.y;
        rawA = rawB; eaA = eaB;
        rawB = rawC; eaB = eaC;
    }
    float inv = 1.f / denom;
    float* od = outv + (size_t)d * D2 + gc;
    float4 o = {acc.x * inv, acc.y * inv, acc.z * inv, acc.w * inv};
    __stcs((float4*)&od[0], o);
}

// ---------------- bias + (silu) + rmsnorm ----------------
__global__ void postact_rms_k(const float* __restrict__ acc, const float* __restrict__ bias,
                              const float* __restrict__ w, float* __restrict__ out,
                              int D, int do_silu) {
    int n = blockIdx.x;
    float vals[2];
    float ss = 0.f;
    int nv = 0;
    for (int j = threadIdx.x; j < D; j += blockDim.x) {
        float v = acc[(size_t)n * D + j] + bias[j];
        if (do_silu) v = v / (1.f + __expf(-v));
        vals[nv++] = v;
        ss += v * v;
    }
    __shared__ float red[32];
    int lane = threadIdx.x & 31, wid = threadIdx.x >> 5;
#pragma unroll
    for (int o = 16; o > 0; o >>= 1) ss += __shfl_down_sync(0xffffffffu, ss, o);
    if (lane == 0) red[wid] = ss;
    __syncthreads();
    if (wid == 0) {
        float s2 = (lane < (blockDim.x >> 5)) ? red[lane] : 0.f;
#pragma unroll
        for (int o = 16; o > 0; o >>= 1) s2 += __shfl_down_sync(0xffffffffu, s2, o);
        if (lane == 0) red[0] = s2;
    }
    __syncthreads();
    float inv = rsqrtf(red[0] / (float)D + EPS);
    nv = 0;
    for (int j = threadIdx.x; j < D; j += blockDim.x)
        out[(size_t)n * D + j] = vals[nv++] * inv * w[j];
}

// ---------------- classifier: warp per node, h row read once ----------------
__global__ __launch_bounds__(256) void out_gemm_k(const float* __restrict__ h,
                                                  const float* __restrict__ W,
                                                  float* __restrict__ out) {
    __shared__ float Ws[NCLS * D2];
    for (int i = threadIdx.x; i < NCLS * D2; i += 256) Ws[i] = W[i];
    __syncthreads();
    int warp = threadIdx.x >> 5;
    int lane = threadIdx.x & 31;
    int n = blockIdx.x * 8 + warp;
    if (n >= NN) return;
    float4 hv = *(const float4*)&h[(size_t)n * D2 + lane * 4];
#pragma unroll
    for (int c = 0; c < NCLS; c++) {
        const float* wr = Ws + c * D2 + lane * 4;
        float s = hv.x * wr[0] + hv.y * wr[1] + hv.z * wr[2] + hv.w * wr[3];
#pragma unroll
        for (int o = 16; o > 0; o >>= 1) s += __shfl_xor_sync(0xffffffffu, s, o);
        if (lane == 0) out[(size_t)n * NCLS + c] = s;
    }
}

// ---------------- launch ----------------
static void* sym(const void* s) {
    void* p = nullptr;
    cudaGetSymbolAddress(&p, s);
    return p;
}

extern "C" void kernel_launch(void* const* d_in, const int* in_sizes, int n_in,
                              void* d_out, int out_size) {
    const float* x     = (const float*)d_in[0];
    const int*   ei    = (const int*)d_in[1];
    const float* eattr = (const float*)d_in[2];
    const float* Wl1   = (const float*)d_in[3];
    const float* bl1   = (const float*)d_in[4];
    const float* Wr1   = (const float*)d_in[5];
    const float* br1   = (const float*)d_in[6];
    const float* We1   = (const float*)d_in[7];
    const float* att1  = (const float*)d_in[8];
    const float* bias1 = (const float*)d_in[9];
    const float* Wl2   = (const float*)d_in[10];
    const float* bl2   = (const float*)d_in[11];
    const float* Wr2   = (const float*)d_in[12];
    const float* br2   = (const float*)d_in[13];
    const float* We2   = (const float*)d_in[14];
    const float* att2  = (const float*)d_in[15];
    const float* bias2 = (const float*)d_in[16];
    const float* w_ln1 = (const float*)d_in[17];
    const float* w_ln3 = (const float*)d_in[18];
    const float* W_out = (const float*)d_in[19];
    float* out = (float*)d_out;

    const int* srcp = ei;
    const int* dstp = ei + NE;

    half* xlh1  = (half*)sym(g_xlh1);
    float* xr1  = (float*)sym(g_xr1);
    half* xlh2  = (half*)sym(g_xlh2);
    float* xr2  = (float*)sym(g_xr2);
    float* acc1 = (float*)sym(g_acc1);
    float* acc2 = (float*)sym(g_acc2);
    int* deg    = (int*)sym(g_deg);
    int* off    = (int*)sym(g_off);
    int* cursor = (int*)sym(g_cursor);
    int* srcs   = (int*)sym(g_srcs);
    float* eas  = (float*)sym(g_eas);

    // 0-2: CSR histogram + scan
    zero_deg_k<<<(NN + 255) / 256, 256>>>(deg);
    hist_k<<<(NE + 255) / 256, 256>>>(dstp, deg);
    scan_k<<<1, 1024>>>(deg, off, cursor);

    // 3: layer 1 fused transforms (profiler capture slot)
    dim3 g1(2 * D1 / 64, (NN + 127) / 128);
    gemm_f16_k<<<g1, 256>>>(x, Wl1, Wr1, bl1, br1, xlh1, xr1, NN, D1, D2);

    // 4: permute edges into CSR order
    scatter_k<<<(NE + 255) / 256, 256>>>(srcp, dstp, eattr, cursor, srcs, eas);

    // 5: CSR edge pass layer 1
    gat_edge1_k<<<(NN * H * 32 + 255) / 256, 256>>>(srcs, eas, off, xlh1, xr1, We1, att1, acc1);

    // 6: silu + rmsnorm
    postact_rms_k<<<NN, 256>>>(acc1, bias1, w_ln1, acc1, D1, 1);

    // 7: layer 2 fused transforms
    dim3 g2(2 * D2 / 64, (NN + 127) / 128);
    gemm_f16_k<<<g2, 256>>>(acc1, Wl2, Wr2, bl2, br2, xlh2, xr2, NN, D2, D1);

    // 8: CSR edge pass layer 2
    gat_edge2_k<<<(NN * 32 + 255) / 256, 256>>>(srcs, eas, off, xlh2, xr2, We2, att2, acc2);

    // 9: rmsnorm
    postact_rms_k<<<NN, 128>>>(acc2, bias2, w_ln3, acc2, D2, 0);

    // 10: classifier — warp per node
    out_gemm_k<<<(NN + 7) / 8, 256>>>(acc2, W_out, out);
}

// round 13
// speedup vs baseline: 1.4498x; 1.0248x over previous
#include <cuda_runtime.h>
#include <cuda_fp16.h>
#include <cuda_bf16.h>

#define NN 30000
#define NE 240000
#define D1 512
#define D2 128
#define H 2
#define C1 256
#define C2 64
#define NCLS 20
#define EPS 1e-5f
#define NEG 0.2f

// ---------------- scratch ----------------
__device__ half g_xlh1[(size_t)NN * D1];
__device__ float g_xr1[(size_t)NN * D1];
__device__ half g_xlh2[(size_t)NN * D2];
__device__ float g_xr2[(size_t)NN * D2];
__device__ float g_acc1[(size_t)NN * D1];
__device__ float g_acc2[(size_t)NN * D2];
__device__ int g_deg[NN];
__device__ int g_off[NN + 1];
__device__ int g_cursor[NN];
__device__ int g_srcs[NE];
__device__ float g_eas[NE];

// ---------------- CSR build ----------------
__global__ void zero_deg_k(int* deg) {
    int i = blockIdx.x * blockDim.x + threadIdx.x;
    if (i < NN) deg[i] = 0;
}
__global__ void hist_k(const int* __restrict__ dst, int* __restrict__ deg) {
    int e = blockIdx.x * blockDim.x + threadIdx.x;
    if (e < NE) atomicAdd(&deg[dst[e]], 1);
}
__global__ __launch_bounds__(1024) void scan_k(const int* __restrict__ deg,
                                               int* __restrict__ off, int* __restrict__ cursor) {
    __shared__ int partial[1024];
    int t = threadIdx.x;
    const int CH = (NN + 1023) / 1024;
    int base = t * CH;
    int s = 0;
    for (int i = 0; i < CH; i++) {
        int idx = base + i;
        if (idx < NN) s += deg[idx];
    }
    partial[t] = s;
    __syncthreads();
    for (int o = 1; o < 1024; o <<= 1) {
        int v = (t >= o) ? partial[t - o] : 0;
        __syncthreads();
        partial[t] += v;
        __syncthreads();
    }
    int run = (t == 0) ? 0 : partial[t - 1];
    for (int i = 0; i < CH; i++) {
        int idx = base + i;
        if (idx < NN) {
            off[idx] = run;
            cursor[idx] = run;
            run += deg[idx];
        }
    }
    if (t == 1023) off[NN] = partial[1023];
}
__global__ void scatter_k(const int* __restrict__ src, const int* __restrict__ dst,
                          const float* __restrict__ eattr, int* __restrict__ cursor,
                          int* __restrict__ srcs, float* __restrict__ eas) {
    int e = blockIdx.x * blockDim.x + threadIdx.x;
    if (e < NE) {
        int pos = atomicAdd(&cursor[dst[e]], 1);
        srcs[pos] = src[e];
        eas[pos] = eattr[e];
    }
}

// ---------------- fp16 MMA ----------------
__device__ __forceinline__ void mma_f16(float* c, const unsigned* a, const unsigned* b) {
    asm volatile(
        "mma.sync.aligned.m16n8k16.row.col.f32.f16.f16.f32 "
        "{%0,%1,%2,%3}, {%4,%5,%6,%7}, {%8,%9}, {%0,%1,%2,%3};\n"
        : "+f"(c[0]), "+f"(c[1]), "+f"(c[2]), "+f"(c[3])
        : "r"(a[0]), "r"(a[1]), "r"(a[2]), "r"(a[3]), "r"(b[0]), "r"(b[1]));
}
__device__ __forceinline__ unsigned pack_h2(float f0, float f1) {
    __half2 h = __floats2half2_rn(f0, f1);
    return *(unsigned*)&h;
}

// ---------------- A-resident dual-B fp16 TC GEMM ----------------
// Block: 128 rows. A chunk (128 x 128 k) resident in smem; loop NT col-tiles of 64,
// reloading only B. KC k-chunks of 128 (accumulators persist across chunks).
// smem stride 68 u32/row -> conflict-free fragment LDS ((4g+t) mod 32 distinct).
#define GEMM_SMEM ((128 + 64) * 68 * 4)
template <int NT, int KC>
__global__ __launch_bounds__(256) void gemm_f16_tile_k(
    const float* __restrict__ A,
    const float* __restrict__ B0, const float* __restrict__ B1,
    const float* __restrict__ bias0, const float* __restrict__ bias1,
    half* __restrict__ Cl, float* __restrict__ Cr, int M, int Nhalf, int K) {
    extern __shared__ unsigned smemu[];
    unsigned(*Asm)[68] = (unsigned(*)[68])smemu;
    unsigned(*Bsm)[68] = (unsigned(*)[68])(smemu + 128 * 68);

    const int tid = threadIdx.x;
    const int lane = tid & 31;
    const int warp = tid >> 5;
    const int wm = warp >> 1;       // 0..3: 32-row slab
    const int wn = warp & 1;        // 0..1: 32-col slab
    const int groupID = lane >> 2;
    const int tg = lane & 3;

    const int bm = blockIdx.y * 128;
    const int bn_base = blockIdx.x * NT * 64;

    constexpr int ACCN = (KC == 1) ? 1 : NT;
    float acc[ACCN][2][4][4] = {};

    for (int kc = 0; kc < KC; kc++) {
        __syncthreads();   // all warps done reading previous A chunk
        // load A chunk: 128 rows x 128 k-floats -> fp16 pairs
#pragma unroll
        for (int j = 0; j < 16; j++) {
            int idx = tid + j * 256;
            int row = idx >> 5;
            int q = idx & 31;
            int gr = bm + row;
            if (gr >= M) gr = M - 1;
            float4 v = *(const float4*)&A[(size_t)gr * K + kc * 128 + q * 4];
            uint2 pp;
            pp.x = pack_h2(v.x, v.y);
            pp.y = pack_h2(v.z, v.w);
            *(uint2*)&Asm[row][q * 2] = pp;
        }
        for (int ct = 0; ct < NT; ct++) {
            __syncthreads();   // prev col-tile done reading Bsm (and A stores arrive, 1st iter)
            // load B tile: 64 rows x 128 k-floats
#pragma unroll
            for (int j = 0; j < 8; j++) {
                int idx = tid + j * 256;
                int row = idx >> 5;
                int q = idx & 31;
                int gn = bn_base + ct * 64 + row;
                const float* Bp = (gn < Nhalf) ? B0 : B1;
                int col = (gn < Nhalf) ? gn : gn - Nhalf;
                float4 v = *(const float4*)&Bp[(size_t)col * K + kc * 128 + q * 4];
                uint2 pp;
                pp.x = pack_h2(v.x, v.y);
                pp.y = pack_h2(v.z, v.w);
                *(uint2*)&Bsm[row][q * 2] = pp;
            }
            __syncthreads();   // A + B resident
            const int ai = (KC == 1) ? 0 : ct;
#pragma unroll
            for (int kt = 0; kt < 8; kt++) {
                unsigned ah[2][4], bh[4][2];
#pragma unroll
                for (int mt = 0; mt < 2; mt++) {
                    int r = wm * 32 + mt * 16 + groupID;
                    ah[mt][0] = Asm[r][kt * 8 + tg];
                    ah[mt][1] = Asm[r + 8][kt * 8 + tg];
                    ah[mt][2] = Asm[r][kt * 8 + tg + 4];
                    ah[mt][3] = Asm[r + 8][kt * 8 + tg + 4];
                }
#pragma unroll
                for (int nt = 0; nt < 4; nt++) {
                    int n = wn * 32 + nt * 8 + groupID;
                    bh[nt][0] = Bsm[n][kt * 8 + tg];
                    bh[nt][1] = Bsm[n][kt * 8 + tg + 4];
                }
#pragma unroll
                for (int mt = 0; mt < 2; mt++)
#pragma unroll
                    for (int nt = 0; nt < 4; nt++)
                        mma_f16(acc[ai][mt][nt], ah[mt], bh[nt]);
            }
            if (KC == 1) {
                // epilogue for this col tile, then reset accumulator
                int cb = bn_base + ct * 64;
#pragma unroll
                for (int mt = 0; mt < 2; mt++) {
                    int row0 = bm + wm * 32 + mt * 16 + groupID;
#pragma unroll
                    for (int nt = 0; nt < 4; nt++) {
                        int col0 = cb + wn * 32 + nt * 8 + tg * 2;
                        float* a4 = acc[0][mt][nt];
                        if (col0 < Nhalf) {
                            float b0 = bias0[col0], b1 = bias0[col0 + 1];
                            if (row0 < M)
                                *(__half2*)&Cl[(size_t)row0 * Nhalf + col0] =
                                    __floats2half2_rn(a4[0] + b0, a4[1] + b1);
                            if (row0 + 8 < M)
                                *(__half2*)&Cl[(size_t)(row0 + 8) * Nhalf + col0] =
                                    __floats2half2_rn(a4[2] + b0, a4[3] + b1);
                        } else {
                            int cc = col0 - Nhalf;
                            float b0 = bias1[cc], b1 = bias1[cc + 1];
                            if (row0 < M) {
                                Cr[(size_t)row0 * Nhalf + cc] = a4[0] + b0;
                                Cr[(size_t)row0 * Nhalf + cc + 1] = a4[1] + b1;
                            }
                            if (row0 + 8 < M) {
                                Cr[(size_t)(row0 + 8) * Nhalf + cc] = a4[2] + b0;
                                Cr[(size_t)(row0 + 8) * Nhalf + cc + 1] = a4[3] + b1;
                            }
                        }
                        a4[0] = a4[1] = a4[2] = a4[3] = 0.f;
                    }
                }
            }
        }
    }
    if (KC > 1) {
#pragma unroll
        for (int ct = 0; ct < NT; ct++) {
            int cb = bn_base + ct * 64;
#pragma unroll
            for (int mt = 0; mt < 2; mt++) {
                int row0 = bm + wm * 32 + mt * 16 + groupID;
#pragma unroll
                for (int nt = 0; nt < 4; nt++) {
                    int col0 = cb + wn * 32 + nt * 8 + tg * 2;
                    float* a4 = acc[(KC == 1) ? 0 : ct][mt][nt];
                    if (col0 < Nhalf) {
                        float b0 = bias0[col0], b1 = bias0[col0 + 1];
                        if (row0 < M)
                            *(__half2*)&Cl[(size_t)row0 * Nhalf + col0] =
                                __floats2half2_rn(a4[0] + b0, a4[1] + b1);
                        if (row0 + 8 < M)
                            *(__half2*)&Cl[(size_t)(row0 + 8) * Nhalf + col0] =
                                __floats2half2_rn(a4[2] + b0, a4[3] + b1);
                    } else {
                        int cc = col0 - Nhalf;
                        float b0 = bias1[cc], b1 = bias1[cc + 1];
                        if (row0 < M) {
                            Cr[(size_t)row0 * Nhalf + cc] = a4[0] + b0;
                            Cr[(size_t)row0 * Nhalf + cc + 1] = a4[1] + b1;
                        }
                        if (row0 + 8 < M) {
                            Cr[(size_t)(row0 + 8) * Nhalf + cc] = a4[2] + b0;
                            Cr[(size_t)(row0 + 8) * Nhalf + cc + 1] = a4[3] + b1;
                        }
                    }
                }
            }
        }
    }
}

// ---------------- CSR edge pass, layer 1 (C=256): warp per (dst, head), prefetch-2 ----------------
__global__ __launch_bounds__(256) void gat_edge1_k(
    const int* __restrict__ srcs, const float* __restrict__ eas,
    const int* __restrict__ off,
    const half* __restrict__ xlh, const float* __restrict__ xr,
    const float* __restrict__ We, const float* __restrict__ att,
    float* __restrict__ outv) {
    int gw = (blockIdx.x * 256 + threadIdx.x) >> 5;
    int lane = threadIdx.x & 31;
    if (gw >= NN * H) return;
    int h = gw & 1;
    int d = gw >> 1;
    const int cb = h * C1 + lane * 8;

    float4 xr_a = __ldcs((const float4*)&xr[(size_t)d * D1 + cb]);
    float4 xr_b = __ldcs((const float4*)&xr[(size_t)d * D1 + cb + 4]);
    float4 w_a = *(const float4*)&We[cb];
    float4 w_b = *(const float4*)&We[cb + 4];
    float4 t_a = *(const float4*)&att[cb];
    float4 t_b = *(const float4*)&att[cb + 4];

    float4 acc_a = {0, 0, 0, 0}, acc_b = {0, 0, 0, 0};
    float denom = 0.f;
    int i0 = off[d], i1 = off[d + 1];
    int degn = i1 - i0;
    float invdeg = 1.f / fmaxf((float)degn, 1.f);
    float easum = 0.f;

    auto ld = [&](int j, uint4& raw, float& ea) {
        int s;
        if (j < i1) {
            s = srcs[j];
            ea = eas[j];
            easum += ea;
        } else {
            s = d;
            ea = easum * invdeg;
        }
        raw = *(const uint4*)&xlh[(size_t)s * D1 + cb];
    };

    uint4 rawA, rawB, rawC;
    float eaA, eaB, eaC;
    ld(i0, rawA, eaA);
    if (i0 + 1 <= i1) ld(i0 + 1, rawB, eaB);

    for (int i = i0; i <= i1; i++) {
        if (i + 2 <= i1) ld(i + 2, rawC, eaC);
        const __half2* hp = (const __half2*)&rawA;
        float2 f0 = __half22float2(hp[0]);
        float2 f1 = __half22float2(hp[1]);
        float2 f2 = __half22float2(hp[2]);
        float2 f3 = __half22float2(hp[3]);
        float eac = eaA;
        float v, lg = 0.f;
        v = f0.x + xr_a.x + eac * w_a.x; v = v > 0.f ? v : NEG * v; lg += v * t_a.x;
        v = f0.y + xr_a.y + eac * w_a.y; v = v > 0.f ? v : NEG * v; lg += v * t_a.y;
        v = f1.x + xr_a.z + eac * w_a.z; v = v > 0.f ? v : NEG * v; lg += v * t_a.z;
        v = f1.y + xr_a.w + eac * w_a.w; v = v > 0.f ? v : NEG * v; lg += v * t_a.w;
        v = f2.x + xr_b.x + eac * w_b.x; v = v > 0.f ? v : NEG * v; lg += v * t_b.x;
        v = f2.y + xr_b.y + eac * w_b.y; v = v > 0.f ? v : NEG * v; lg += v * t_b.y;
        v = f3.x + xr_b.z + eac * w_b.z; v = v > 0.f ? v : NEG * v; lg += v * t_b.z;
        v = f3.y + xr_b.w + eac * w_b.w; v = v > 0.f ? v : NEG * v; lg += v * t_b.w;
#pragma unroll
        for (int o = 16; o > 0; o >>= 1) lg += __shfl_xor_sync(0xffffffffu, lg, o);
        float p = __expf(lg);
        denom += p;
        acc_a.x += p * f0.x; acc_a.y += p * f0.y; acc_a.z += p * f1.x; acc_a.w += p * f1.y;
        acc_b.x += p * f2.x; acc_b.y += p * f2.y; acc_b.z += p * f3.x; acc_b.w += p * f3.y;
        rawA = rawB; eaA = eaB;
        rawB = rawC; eaB = eaC;
    }
    float inv = 1.f / denom;
    float* od = outv + (size_t)d * D1 + cb;
    float4 o_a = {acc_a.x * inv, acc_a.y * inv, acc_a.z * inv, acc_a.w * inv};
    float4 o_b = {acc_b.x * inv, acc_b.y * inv, acc_b.z * inv, acc_b.w * inv};
    __stcs((float4*)&od[0], o_a);
    __stcs((float4*)&od[4], o_b);
}

// ---------------- CSR edge pass, layer 2 (C=64): warp per dst, prefetch-2 ----------------
__global__ __launch_bounds__(256) void gat_edge2_k(
    const int* __restrict__ srcs, const float* __restrict__ eas,
    const int* __restrict__ off,
    const half* __restrict__ xlh, const float* __restrict__ xr,
    const float* __restrict__ We, const float* __restrict__ att,
    float* __restrict__ outv) {
    int gw = (blockIdx.x * 256 + threadIdx.x) >> 5;
    int lane = threadIdx.x & 31;
    if (gw >= NN) return;
    int d = gw;
    int h = lane >> 4;
    int cl = (lane & 15) * 4;
    int gc = h * C2 + cl;

    float4 xr_v = __ldcs((const float4*)&xr[(size_t)d * D2 + gc]);
    float4 w_v = *(const float4*)&We[gc];
    float4 t_v = *(const float4*)&att[gc];

    float4 acc = {0, 0, 0, 0};
    float denom = 0.f;
    int i0 = off[d], i1 = off[d + 1];
    int degn = i1 - i0;
    float invdeg = 1.f / fmaxf((float)degn, 1.f);
    float easum = 0.f;

    auto ld = [&](int j, uint2& raw, float& ea) {
        int s;
        if (j < i1) {
            s = srcs[j];
            ea = eas[j];
            easum += ea;
        } else {
            s = d;
            ea = easum * invdeg;
        }
        raw = *(const uint2*)&xlh[(size_t)s * D2 + gc];
    };

    uint2 rawA, rawB, rawC;
    float eaA, eaB, eaC;
    ld(i0, rawA, eaA);
    if (i0 + 1 <= i1) ld(i0 + 1, rawB, eaB);

    for (int i = i0; i <= i1; i++) {
        if (i + 2 <= i1) ld(i + 2, rawC, eaC);
        const __half2* hp = (const __half2*)&rawA;
        float2 f0 = __half22float2(hp[0]);
        float2 f1 = __half22float2(hp[1]);
        float eac = eaA;
        float v, lg = 0.f;
        v = f0.x + xr_v.x + eac * w_v.x; v = v > 0.f ? v : NEG * v; lg += v * t_v.x;
        v = f0.y + xr_v.y + eac * w_v.y; v = v > 0.f ? v : NEG * v; lg += v * t_v.y;
        v = f1.x + xr_v.z + eac * w_v.z; v = v > 0.f ? v : NEG * v; lg += v * t_v.z;
        v = f1.y + xr_v.w + eac * w_v.w; v = v > 0.f ? v : NEG * v; lg += v * t_v.w;
#pragma unroll
        for (int o = 8; o > 0; o >>= 1) lg += __shfl_xor_sync(0xffffffffu, lg, o);
        float p = __expf(lg);
        denom += p;
        acc.x += p * f0.x; acc.y += p * f0.y; acc.z += p * f1.x; acc.w += p * f1.y;
        rawA = rawB; eaA = eaB;
        rawB = rawC; eaB = eaC;
    }
    float inv = 1.f / denom;
    float* od = outv + (size_t)d * D2 + gc;
    float4 o = {acc.x * inv, acc.y * inv, acc.z * inv, acc.w * inv};
    __stcs((float4*)&od[0], o);
}

// ---------------- bias + (silu) + rmsnorm ----------------
__global__ void postact_rms_k(const float* __restrict__ acc, const float* __restrict__ bias,
                              const float* __restrict__ w, float* __restrict__ out,
                              int D, int do_silu) {
    int n = blockIdx.x;
    float vals[2];
    float ss = 0.f;
    int nv = 0;
    for (int j = threadIdx.x; j < D; j += blockDim.x) {
        float v = acc[(size_t)n * D + j] + bias[j];
        if (do_silu) v = v / (1.f + __expf(-v));
        vals[nv++] = v;
        ss += v * v;
    }
    __shared__ float red[32];
    int lane = threadIdx.x & 31, wid = threadIdx.x >> 5;
#pragma unroll
    for (int o = 16; o > 0; o >>= 1) ss += __shfl_down_sync(0xffffffffu, ss, o);
    if (lane == 0) red[wid] = ss;
    __syncthreads();
    if (wid == 0) {
        float s2 = (lane < (blockDim.x >> 5)) ? red[lane] : 0.f;
#pragma unroll
        for (int o = 16; o > 0; o >>= 1) s2 += __shfl_down_sync(0xffffffffu, s2, o);
        if (lane == 0) red[0] = s2;
    }
    __syncthreads();
    float inv = rsqrtf(red[0] / (float)D + EPS);
    nv = 0;
    for (int j = threadIdx.x; j < D; j += blockDim.x)
        out[(size_t)n * D + j] = vals[nv++] * inv * w[j];
}

// ---------------- classifier: warp per node ----------------
__global__ __launch_bounds__(256) void out_gemm_k(const float* __restrict__ h,
                                                  const float* __restrict__ W,
                                                  float* __restrict__ out) {
    __shared__ float Ws[NCLS * D2];
    for (int i = threadIdx.x; i < NCLS * D2; i += 256) Ws[i] = W[i];
    __syncthreads();
    int warp = threadIdx.x >> 5;
    int lane = threadIdx.x & 31;
    int n = blockIdx.x * 8 + warp;
    if (n >= NN) return;
    float4 hv = *(const float4*)&h[(size_t)n * D2 + lane * 4];
#pragma unroll
    for (int c = 0; c < NCLS; c++) {
        const float* wr = Ws + c * D2 + lane * 4;
        float s = hv.x * wr[0] + hv.y * wr[1] + hv.z * wr[2] + hv.w * wr[3];
#pragma unroll
        for (int o = 16; o > 0; o >>= 1) s += __shfl_xor_sync(0xffffffffu, s, o);
        if (lane == 0) out[(size_t)n * NCLS + c] = s;
    }
}

// ---------------- launch ----------------
static void* sym(const void* s) {
    void* p = nullptr;
    cudaGetSymbolAddress(&p, s);
    return p;
}

extern "C" void kernel_launch(void* const* d_in, const int* in_sizes, int n_in,
                              void* d_out, int out_size) {
    const float* x     = (const float*)d_in[0];
    const int*   ei    = (const int*)d_in[1];
    const float* eattr = (const float*)d_in[2];
    const float* Wl1   = (const float*)d_in[3];
    const float* bl1   = (const float*)d_in[4];
    const float* Wr1   = (const float*)d_in[5];
    const float* br1   = (const float*)d_in[6];
    const float* We1   = (const float*)d_in[7];
    const float* att1  = (const float*)d_in[8];
    const float* bias1 = (const float*)d_in[9];
    const float* Wl2   = (const float*)d_in[10];
    const float* bl2   = (const float*)d_in[11];
    const float* Wr2   = (const float*)d_in[12];
    const float* br2   = (const float*)d_in[13];
    const float* We2   = (const float*)d_in[14];
    const float* att2  = (const float*)d_in[15];
    const float* bias2 = (const float*)d_in[16];
    const float* w_ln1 = (const float*)d_in[17];
    const float* w_ln3 = (const float*)d_in[18];
    const float* W_out = (const float*)d_in[19];
    float* out = (float*)d_out;

    const int* srcp = ei;
    const int* dstp = ei + NE;

    half* xlh1  = (half*)sym(g_xlh1);
    float* xr1  = (float*)sym(g_xr1);
    half* xlh2  = (half*)sym(g_xlh2);
    float* xr2  = (float*)sym(g_xr2);
    float* acc1 = (float*)sym(g_acc1);
    float* acc2 = (float*)sym(g_acc2);
    int* deg    = (int*)sym(g_deg);
    int* off    = (int*)sym(g_off);
    int* cursor = (int*)sym(g_cursor);
    int* srcs   = (int*)sym(g_srcs);
    float* eas  = (float*)sym(g_eas);

    cudaFuncSetAttribute(gemm_f16_tile_k<8, 1>,
                         cudaFuncAttributeMaxDynamicSharedMemorySize, GEMM_SMEM);
    cudaFuncSetAttribute(gemm_f16_tile_k<2, 4>,
                         cudaFuncAttributeMaxDynamicSharedMemorySize, GEMM_SMEM);

    // 0-2: CSR histogram + scan
    zero_deg_k<<<(NN + 255) / 256, 256>>>(deg);
    hist_k<<<(NE + 255) / 256, 256>>>(dstp, deg);
    scan_k<<<1, 1024>>>(deg, off, cursor);

    // 3: layer 1 transforms (profiler capture slot): NT=8 col tiles, KC=1
    dim3 g1(2, (NN + 127) / 128);
    gemm_f16_tile_k<8, 1><<<g1, 256, GEMM_SMEM>>>(x, Wl1, Wr1, bl1, br1, xlh1, xr1, NN, D1, D2);

    // 4: permute edges into CSR order
    scatter_k<<<(NE + 255) / 256, 256>>>(srcp, dstp, eattr, cursor, srcs, eas);

    // 5: CSR edge pass layer 1
    gat_edge1_k<<<(NN * H * 32 + 255) / 256, 256>>>(srcs, eas, off, xlh1, xr1, We1, att1, acc1);

    // 6: silu + rmsnorm
    postact_rms_k<<<NN, 256>>>(acc1, bias1, w_ln1, acc1, D1, 1);

    // 7: layer 2 transforms: NT=2 col tiles, KC=4 (K=512)
    dim3 g2(2, (NN + 127) / 128);
    gemm_f16_tile_k<2, 4><<<g2, 256, GEMM_SMEM>>>(acc1, Wl2, Wr2, bl2, br2, xlh2, xr2, NN, D2, D1);

    // 8: CSR edge pass layer 2
    gat_edge2_k<<<(NN * 32 + 255) / 256, 256>>>(srcs, eas, off, xlh2, xr2, We2, att2, acc2);

    // 9: rmsnorm
    postact_rms_k<<<NN, 128>>>(acc2, bias2, w_ln3, acc2, D2, 0);

    // 10: classifier — warp per node
    out_gemm_k<<<(NN + 7) / 8, 256>>>(acc2, W_out, out);
}

// round 14
// speedup vs baseline: 1.4504x; 1.0004x over previous
#include <cuda_runtime.h>
#include <cuda_fp16.h>
#include <cuda_bf16.h>

#define NN 30000
#define NE 240000
#define D1 512
#define D2 128
#define H 2
#define C1 256
#define C2 64
#define NCLS 20
#define EPS 1e-5f
#define NEG 0.2f

// ---------------- scratch ----------------
__device__ half g_xlh1[(size_t)NN * D1];
__device__ float g_xr1[(size_t)NN * D1];
__device__ half g_xlh2[(size_t)NN * D2];
__device__ float g_xr2[(size_t)NN * D2];
__device__ float g_acc1[(size_t)NN * D1];
__device__ float g_acc2[(size_t)NN * D2];
__device__ int g_deg[NN];
__device__ int g_off[NN + 1];
__device__ int g_cursor[NN];
__device__ int g_srcs[NE];
__device__ float g_eas[NE];

// ---------------- CSR build ----------------
__global__ void zero_deg_k(int* deg) {
    int i = blockIdx.x * blockDim.x + threadIdx.x;
    if (i < NN) deg[i] = 0;
}
__global__ void hist_k(const int* __restrict__ dst, int* __restrict__ deg) {
    int e = blockIdx.x * blockDim.x + threadIdx.x;
    if (e < NE) atomicAdd(&deg[dst[e]], 1);
}
__global__ __launch_bounds__(1024) void scan_k(const int* __restrict__ deg,
                                               int* __restrict__ off, int* __restrict__ cursor) {
    __shared__ int partial[1024];
    int t = threadIdx.x;
    const int CH = (NN + 1023) / 1024;
    int base = t * CH;
    int s = 0;
    for (int i = 0; i < CH; i++) {
        int idx = base + i;
        if (idx < NN) s += deg[idx];
    }
    partial[t] = s;
    __syncthreads();
    for (int o = 1; o < 1024; o <<= 1) {
        int v = (t >= o) ? partial[t - o] : 0;
        __syncthreads();
        partial[t] += v;
        __syncthreads();
    }
    int run = (t == 0) ? 0 : partial[t - 1];
    for (int i = 0; i < CH; i++) {
        int idx = base + i;
        if (idx < NN) {
            off[idx] = run;
            cursor[idx] = run;
            run += deg[idx];
        }
    }
    if (t == 1023) off[NN] = partial[1023];
}
__global__ void scatter_k(const int* __restrict__ src, const int* __restrict__ dst,
                          const float* __restrict__ eattr, int* __restrict__ cursor,
                          int* __restrict__ srcs, float* __restrict__ eas) {
    int e = blockIdx.x * blockDim.x + threadIdx.x;
    if (e < NE) {
        int pos = atomicAdd(&cursor[dst[e]], 1);
        srcs[pos] = src[e];
        eas[pos] = eattr[e];
    }
}

// ---------------- fp16 MMA ----------------
__device__ __forceinline__ void mma_f16(float* c, const unsigned* a, const unsigned* b) {
    asm volatile(
        "mma.sync.aligned.m16n8k16.row.col.f32.f16.f16.f32 "
        "{%0,%1,%2,%3}, {%4,%5,%6,%7}, {%8,%9}, {%0,%1,%2,%3};\n"
        : "+f"(c[0]), "+f"(c[1]), "+f"(c[2]), "+f"(c[3])
        : "r"(a[0]), "r"(a[1]), "r"(a[2]), "r"(a[3]), "r"(b[0]), "r"(b[1]));
}
__device__ __forceinline__ unsigned pack_h2(float f0, float f1) {
    __half2 h = __floats2half2_rn(f0, f1);
    return *(unsigned*)&h;
}

// ---------------- A-resident dual-B fp16 TC GEMM ----------------
#define GEMM_SMEM ((128 + 64) * 68 * 4)
template <int NT, int KC>
__global__ __launch_bounds__(256) void gemm_f16_tile_k(
    const float* __restrict__ A,
    const float* __restrict__ B0, const float* __restrict__ B1,
    const float* __restrict__ bias0, const float* __restrict__ bias1,
    half* __restrict__ Cl, float* __restrict__ Cr, int M, int Nhalf, int K) {
    extern __shared__ unsigned smemu[];
    unsigned(*Asm)[68] = (unsigned(*)[68])smemu;
    unsigned(*Bsm)[68] = (unsigned(*)[68])(smemu + 128 * 68);

    const int tid = threadIdx.x;
    const int lane = tid & 31;
    const int warp = tid >> 5;
    const int wm = warp >> 1;
    const int wn = warp & 1;
    const int groupID = lane >> 2;
    const int tg = lane & 3;

    const int bm = blockIdx.y * 128;
    const int bn_base = blockIdx.x * NT * 64;

    constexpr int ACCN = (KC == 1) ? 1 : NT;
    float acc[ACCN][2][4][4] = {};

    for (int kc = 0; kc < KC; kc++) {
        __syncthreads();
#pragma unroll
        for (int j = 0; j < 16; j++) {
            int idx = tid + j * 256;
            int row = idx >> 5;
            int q = idx & 31;
            int gr = bm + row;
            if (gr >= M) gr = M - 1;
            float4 v = *(const float4*)&A[(size_t)gr * K + kc * 128 + q * 4];
            uint2 pp;
            pp.x = pack_h2(v.x, v.y);
            pp.y = pack_h2(v.z, v.w);
            *(uint2*)&Asm[row][q * 2] = pp;
        }
        for (int ct = 0; ct < NT; ct++) {
            __syncthreads();
#pragma unroll
            for (int j = 0; j < 8; j++) {
                int idx = tid + j * 256;
                int row = idx >> 5;
                int q = idx & 31;
                int gn = bn_base + ct * 64 + row;
                const float* Bp = (gn < Nhalf) ? B0 : B1;
                int col = (gn < Nhalf) ? gn : gn - Nhalf;
                float4 v = *(const float4*)&Bp[(size_t)col * K + kc * 128 + q * 4];
                uint2 pp;
                pp.x = pack_h2(v.x, v.y);
                pp.y = pack_h2(v.z, v.w);
                *(uint2*)&Bsm[row][q * 2] = pp;
            }
            __syncthreads();
            const int ai = (KC == 1) ? 0 : ct;
#pragma unroll
            for (int kt = 0; kt < 8; kt++) {
                unsigned ah[2][4], bh[4][2];
#pragma unroll
                for (int mt = 0; mt < 2; mt++) {
                    int r = wm * 32 + mt * 16 + groupID;
                    ah[mt][0] = Asm[r][kt * 8 + tg];
                    ah[mt][1] = Asm[r + 8][kt * 8 + tg];
                    ah[mt][2] = Asm[r][kt * 8 + tg + 4];
                    ah[mt][3] = Asm[r + 8][kt * 8 + tg + 4];
                }
#pragma unroll
                for (int nt = 0; nt < 4; nt++) {
                    int n = wn * 32 + nt * 8 + groupID;
                    bh[nt][0] = Bsm[n][kt * 8 + tg];
                    bh[nt][1] = Bsm[n][kt * 8 + tg + 4];
                }
#pragma unroll
                for (int mt = 0; mt < 2; mt++)
#pragma unroll
                    for (int nt = 0; nt < 4; nt++)
                        mma_f16(acc[ai][mt][nt], ah[mt], bh[nt]);
            }
            if (KC == 1) {
                int cb = bn_base + ct * 64;
#pragma unroll
                for (int mt = 0; mt < 2; mt++) {
                    int row0 = bm + wm * 32 + mt * 16 + groupID;
#pragma unroll
                    for (int nt = 0; nt < 4; nt++) {
                        int col0 = cb + wn * 32 + nt * 8 + tg * 2;
                        float* a4 = acc[0][mt][nt];
                        if (col0 < Nhalf) {
                            float b0 = bias0[col0], b1 = bias0[col0 + 1];
                            if (row0 < M)
                                *(__half2*)&Cl[(size_t)row0 * Nhalf + col0] =
                                    __floats2half2_rn(a4[0] + b0, a4[1] + b1);
                            if (row0 + 8 < M)
                                *(__half2*)&Cl[(size_t)(row0 + 8) * Nhalf + col0] =
                                    __floats2half2_rn(a4[2] + b0, a4[3] + b1);
                        } else {
                            int cc = col0 - Nhalf;
                            float b0 = bias1[cc], b1 = bias1[cc + 1];
                            if (row0 < M) {
                                Cr[(size_t)row0 * Nhalf + cc] = a4[0] + b0;
                                Cr[(size_t)row0 * Nhalf + cc + 1] = a4[1] + b1;
                            }
                            if (row0 + 8 < M) {
                                Cr[(size_t)(row0 + 8) * Nhalf + cc] = a4[2] + b0;
                                Cr[(size_t)(row0 + 8) * Nhalf + cc + 1] = a4[3] + b1;
                            }
                        }
                        a4[0] = a4[1] = a4[2] = a4[3] = 0.f;
                    }
                }
            }
        }
    }
    if (KC > 1) {
#pragma unroll
        for (int ct = 0; ct < NT; ct++) {
            int cb = bn_base + ct * 64;
#pragma unroll
            for (int mt = 0; mt < 2; mt++) {
                int row0 = bm + wm * 32 + mt * 16 + groupID;
#pragma unroll
                for (int nt = 0; nt < 4; nt++) {
                    int col0 = cb + wn * 32 + nt * 8 + tg * 2;
                    float* a4 = acc[(KC == 1) ? 0 : ct][mt][nt];
                    if (col0 < Nhalf) {
                        float b0 = bias0[col0], b1 = bias0[col0 + 1];
                        if (row0 < M)
                            *(__half2*)&Cl[(size_t)row0 * Nhalf + col0] =
                                __floats2half2_rn(a4[0] + b0, a4[1] + b1);
                        if (row0 + 8 < M)
                            *(__half2*)&Cl[(size_t)(row0 + 8) * Nhalf + col0] =
                                __floats2half2_rn(a4[2] + b0, a4[3] + b1);
                    } else {
                        int cc = col0 - Nhalf;
                        float b0 = bias1[cc], b1 = bias1[cc + 1];
                        if (row0 < M) {
                            Cr[(size_t)row0 * Nhalf + cc] = a4[0] + b0;
                            Cr[(size_t)row0 * Nhalf + cc + 1] = a4[1] + b1;
                        }
                        if (row0 + 8 < M) {
                            Cr[(size_t)(row0 + 8) * Nhalf + cc] = a4[2] + b0;
                            Cr[(size_t)(row0 + 8) * Nhalf + cc + 1] = a4[3] + b1;
                        }
                    }
                }
            }
        }
    }
}

// ---------------- CSR edge pass, layer 1 (C=256): warp per (dst, head), 2 edges/iter ----------------
__global__ __launch_bounds__(256) void gat_edge1_k(
    const int* __restrict__ srcs, const float* __restrict__ eas,
    const int* __restrict__ off,
    const half* __restrict__ xlh, const float* __restrict__ xr,
    const float* __restrict__ We, const float* __restrict__ att,
    float* __restrict__ outv) {
    int gw = (blockIdx.x * 256 + threadIdx.x) >> 5;
    int lane = threadIdx.x & 31;
    if (gw >= NN * H) return;
    int h = gw & 1;
    int d = gw >> 1;
    const int cb = h * C1 + lane * 8;

    float4 xr_a = __ldcs((const float4*)&xr[(size_t)d * D1 + cb]);
    float4 xr_b = __ldcs((const float4*)&xr[(size_t)d * D1 + cb + 4]);
    float4 w_a = *(const float4*)&We[cb];
    float4 w_b = *(const float4*)&We[cb + 4];
    float4 t_a = *(const float4*)&att[cb];
    float4 t_b = *(const float4*)&att[cb + 4];

    float4 acc_a = {0, 0, 0, 0}, acc_b = {0, 0, 0, 0};
    float denom = 0.f;
    int i0 = off[d], i1 = off[d + 1];
    int degn = i1 - i0;
    float invdeg = 1.f / fmaxf((float)degn, 1.f);
    float easum = 0.f;

    int i = i0;
    while (i <= i1) {
        // edge A
        int sA;
        float eaA;
        if (i < i1) {
            sA = srcs[i];
            eaA = eas[i];
            easum += eaA;
        } else {
            sA = d;
            eaA = easum * invdeg;
        }
        uint4 rawA = *(const uint4*)&xlh[(size_t)sA * D1 + cb];
        // edge B (or dummy copy of A with weight 0)
        bool two = (i + 1) <= i1;
        float wB = two ? 1.f : 0.f;
        int sB = sA;
        float eaB = eaA;
        if (two) {
            if (i + 1 < i1) {
                sB = srcs[i + 1];
                eaB = eas[i + 1];
                easum += eaB;
            } else {
                sB = d;
                eaB = easum * invdeg;
            }
        }
        uint4 rawB = *(const uint4*)&xlh[(size_t)sB * D1 + cb];

        const __half2* hA = (const __half2*)&rawA;
        const __half2* hB = (const __half2*)&rawB;
        float2 a0 = __half22float2(hA[0]), b0 = __half22float2(hB[0]);
        float2 a1 = __half22float2(hA[1]), b1 = __half22float2(hB[1]);
        float2 a2 = __half22float2(hA[2]), b2 = __half22float2(hB[2]);
        float2 a3 = __half22float2(hA[3]), b3 = __half22float2(hB[3]);

        float v, lgA = 0.f, lgB = 0.f;
        v = a0.x + xr_a.x + eaA * w_a.x; v = v > 0.f ? v : NEG * v; lgA += v * t_a.x;
        v = b0.x + xr_a.x + eaB * w_a.x; v = v > 0.f ? v : NEG * v; lgB += v * t_a.x;
        v = a0.y + xr_a.y + eaA * w_a.y; v = v > 0.f ? v : NEG * v; lgA += v * t_a.y;
        v = b0.y + xr_a.y + eaB * w_a.y; v = v > 0.f ? v : NEG * v; lgB += v * t_a.y;
        v = a1.x + xr_a.z + eaA * w_a.z; v = v > 0.f ? v : NEG * v; lgA += v * t_a.z;
        v = b1.x + xr_a.z + eaB * w_a.z; v = v > 0.f ? v : NEG * v; lgB += v * t_a.z;
        v = a1.y + xr_a.w + eaA * w_a.w; v = v > 0.f ? v : NEG * v; lgA += v * t_a.w;
        v = b1.y + xr_a.w + eaB * w_a.w; v = v > 0.f ? v : NEG * v; lgB += v * t_a.w;
        v = a2.x + xr_b.x + eaA * w_b.x; v = v > 0.f ? v : NEG * v; lgA += v * t_b.x;
        v = b2.x + xr_b.x + eaB * w_b.x; v = v > 0.f ? v : NEG * v; lgB += v * t_b.x;
        v = a2.y + xr_b.y + eaA * w_b.y; v = v > 0.f ? v : NEG * v; lgA += v * t_b.y;
        v = b2.y + xr_b.y + eaB * w_b.y; v = v > 0.f ? v : NEG * v; lgB += v * t_b.y;
        v = a3.x + xr_b.z + eaA * w_b.z; v = v > 0.f ? v : NEG * v; lgA += v * t_b.z;
        v = b3.x + xr_b.z + eaB * w_b.z; v = v > 0.f ? v : NEG * v; lgB += v * t_b.z;
        v = a3.y + xr_b.w + eaA * w_b.w; v = v > 0.f ? v : NEG * v; lgA += v * t_b.w;
        v = b3.y + xr_b.w + eaB * w_b.w; v = v > 0.f ? v : NEG * v; lgB += v * t_b.w;

#pragma unroll
        for (int o = 16; o > 0; o >>= 1) {
            lgA += __shfl_xor_sync(0xffffffffu, lgA, o);
            lgB += __shfl_xor_sync(0xffffffffu, lgB, o);
        }
        float pA = __expf(lgA);
        float pB = wB * __expf(lgB);
        denom += pA + pB;
        acc_a.x += pA * a0.x + pB * b0.x;
        acc_a.y += pA * a0.y + pB * b0.y;
        acc_a.z += pA * a1.x + pB * b1.x;
        acc_a.w += pA * a1.y + pB * b1.y;
        acc_b.x += pA * a2.x + pB * b2.x;
        acc_b.y += pA * a2.y + pB * b2.y;
        acc_b.z += pA * a3.x + pB * b3.x;
        acc_b.w += pA * a3.y + pB * b3.y;
        i += two ? 2 : 1;
    }
    float inv = 1.f / denom;
    float* od = outv + (size_t)d * D1 + cb;
    float4 o_a = {acc_a.x * inv, acc_a.y * inv, acc_a.z * inv, acc_a.w * inv};
    float4 o_b = {acc_b.x * inv, acc_b.y * inv, acc_b.z * inv, acc_b.w * inv};
    __stcs((float4*)&od[0], o_a);
    __stcs((float4*)&od[4], o_b);
}

// ---------------- CSR edge pass, layer 2 (C=64): warp per dst, 2 edges/iter ----------------
__global__ __launch_bounds__(256) void gat_edge2_k(
    const int* __restrict__ srcs, const float* __restrict__ eas,
    const int* __restrict__ off,
    const half* __restrict__ xlh, const float* __restrict__ xr,
    const float* __restrict__ We, const float* __restrict__ att,
    float* __restrict__ outv) {
    int gw = (blockIdx.x * 256 + threadIdx.x) >> 5;
    int lane = threadIdx.x & 31;
    if (gw >= NN) return;
    int d = gw;
    int h = lane >> 4;
    int cl = (lane & 15) * 4;
    int gc = h * C2 + cl;

    float4 xr_v = __ldcs((const float4*)&xr[(size_t)d * D2 + gc]);
    float4 w_v = *(const float4*)&We[gc];
    float4 t_v = *(const float4*)&att[gc];

    float4 acc = {0, 0, 0, 0};
    float denom = 0.f;
    int i0 = off[d], i1 = off[d + 1];
    int degn = i1 - i0;
    float invdeg = 1.f / fmaxf((float)degn, 1.f);
    float easum = 0.f;

    int i = i0;
    while (i <= i1) {
        int sA;
        float eaA;
        if (i < i1) {
            sA = srcs[i];
            eaA = eas[i];
            easum += eaA;
        } else {
            sA = d;
            eaA = easum * invdeg;
        }
        uint2 rawA = *(const uint2*)&xlh[(size_t)sA * D2 + gc];
        bool two = (i + 1) <= i1;
        float wB = two ? 1.f : 0.f;
        int sB = sA;
        float eaB = eaA;
        if (two) {
            if (i + 1 < i1) {
                sB = srcs[i + 1];
                eaB = eas[i + 1];
                easum += eaB;
            } else {
                sB = d;
                eaB = easum * invdeg;
            }
        }
        uint2 rawB = *(const uint2*)&xlh[(size_t)sB * D2 + gc];

        const __half2* hA = (const __half2*)&rawA;
        const __half2* hB = (const __half2*)&rawB;
        float2 a0 = __half22float2(hA[0]), b0 = __half22float2(hB[0]);
        float2 a1 = __half22float2(hA[1]), b1 = __half22float2(hB[1]);

        float v, lgA = 0.f, lgB = 0.f;
        v = a0.x + xr_v.x + eaA * w_v.x; v = v > 0.f ? v : NEG * v; lgA += v * t_v.x;
        v = b0.x + xr_v.x + eaB * w_v.x; v = v > 0.f ? v : NEG * v; lgB += v * t_v.x;
        v = a0.y + xr_v.y + eaA * w_v.y; v = v > 0.f ? v : NEG * v; lgA += v * t_v.y;
        v = b0.y + xr_v.y + eaB * w_v.y; v = v > 0.f ? v : NEG * v; lgB += v * t_v.y;
        v = a1.x + xr_v.z + eaA * w_v.z; v = v > 0.f ? v : NEG * v; lgA += v * t_v.z;
        v = b1.x + xr_v.z + eaB * w_v.z; v = v > 0.f ? v : NEG * v; lgB += v * t_v.z;
        v = a1.y + xr_v.w + eaA * w_v.w; v = v > 0.f ? v : NEG * v; lgA += v * t_v.w;
        v = b1.y + xr_v.w + eaB * w_v.w; v = v > 0.f ? v : NEG * v; lgB += v * t_v.w;

#pragma unroll
        for (int o = 8; o > 0; o >>= 1) {
            lgA += __shfl_xor_sync(0xffffffffu, lgA, o);
            lgB += __shfl_xor_sync(0xffffffffu, lgB, o);
        }
        float pA = __expf(lgA);
        float pB = wB * __expf(lgB);
        denom += pA + pB;
        acc.x += pA * a0.x + pB * b0.x;
        acc.y += pA * a0.y + pB * b0.y;
        acc.z += pA * a1.x + pB * b1.x;
        acc.w += pA * a1.y + pB * b1.y;
        i += two ? 2 : 1;
    }
    float inv = 1.f / denom;
    float* od = outv + (size_t)d * D2 + gc;
    float4 o = {acc.x * inv, acc.y * inv, acc.z * inv, acc.w * inv};
    __stcs((float4*)&od[0], o);
}

// ---------------- bias + (silu) + rmsnorm ----------------
__global__ void postact_rms_k(const float* __restrict__ acc, const float* __restrict__ bias,
                              const float* __restrict__ w, float* __restrict__ out,
                              int D, int do_silu) {
    int n = blockIdx.x;
    float vals[2];
    float ss = 0.f;
    int nv = 0;
    for (int j = threadIdx.x; j < D; j += blockDim.x) {
        float v = acc[(size_t)n * D + j] + bias[j];
        if (do_silu) v = v / (1.f + __expf(-v));
        vals[nv++] = v;
        ss += v * v;
    }
    __shared__ float red[32];
    int lane = threadIdx.x & 31, wid = threadIdx.x >> 5;
#pragma unroll
    for (int o = 16; o > 0; o >>= 1) ss += __shfl_down_sync(0xffffffffu, ss, o);
    if (lane == 0) red[wid] = ss;
    __syncthreads();
    if (wid == 0) {
        float s2 = (lane < (blockDim.x >> 5)) ? red[lane] : 0.f;
#pragma unroll
        for (int o = 16; o > 0; o >>= 1) s2 += __shfl_down_sync(0xffffffffu, s2, o);
        if (lane == 0) red[0] = s2;
    }
    __syncthreads();
    float inv = rsqrtf(red[0] / (float)D + EPS);
    nv = 0;
    for (int j = threadIdx.x; j < D; j += blockDim.x)
        out[(size_t)n * D + j] = vals[nv++] * inv * w[j];
}

// ---------------- classifier: warp per node ----------------
__global__ __launch_bounds__(256) void out_gemm_k(const float* __restrict__ h,
                                                  const float* __restrict__ W,
                                                  float* __restrict__ out) {
    __shared__ float Ws[NCLS * D2];
    for (int i = threadIdx.x; i < NCLS * D2; i += 256) Ws[i] = W[i];
    __syncthreads();
    int warp = threadIdx.x >> 5;
    int lane = threadIdx.x & 31;
    int n = blockIdx.x * 8 + warp;
    if (n >= NN) return;
    float4 hv = *(const float4*)&h[(size_t)n * D2 + lane * 4];
#pragma unroll
    for (int c = 0; c < NCLS; c++) {
        const float* wr = Ws + c * D2 + lane * 4;
        float s = hv.x * wr[0] + hv.y * wr[1] + hv.z * wr[2] + hv.w * wr[3];
#pragma unroll
        for (int o = 16; o > 0; o >>= 1) s += __shfl_xor_sync(0xffffffffu, s, o);
        if (lane == 0) out[(size_t)n * NCLS + c] = s;
    }
}

// ---------------- launch ----------------
static void* sym(const void* s) {
    void* p = nullptr;
    cudaGetSymbolAddress(&p, s);
    return p;
}

extern "C" void kernel_launch(void* const* d_in, const int* in_sizes, int n_in,
                              void* d_out, int out_size) {
    const float* x     = (const float*)d_in[0];
    const int*   ei    = (const int*)d_in[1];
    const float* eattr = (const float*)d_in[2];
    const float* Wl1   = (const float*)d_in[3];
    const float* bl1   = (const float*)d_in[4];
    const float* Wr1   = (const float*)d_in[5];
    const float* br1   = (const float*)d_in[6];
    const float* We1   = (const float*)d_in[7];
    const float* att1  = (const float*)d_in[8];
    const float* bias1 = (const float*)d_in[9];
    const float* Wl2   = (const float*)d_in[10];
    const float* bl2   = (const float*)d_in[11];
    const float* Wr2   = (const float*)d_in[12];
    const float* br2   = (const float*)d_in[13];
    const float* We2   = (const float*)d_in[14];
    const float* att2  = (const float*)d_in[15];
    const float* bias2 = (const float*)d_in[16];
    const float* w_ln1 = (const float*)d_in[17];
    const float* w_ln3 = (const float*)d_in[18];
    const float* W_out = (const float*)d_in[19];
    float* out = (float*)d_out;

    const int* srcp = ei;
    const int* dstp = ei + NE;

    half* xlh1  = (half*)sym(g_xlh1);
    float* xr1  = (float*)sym(g_xr1);
    half* xlh2  = (half*)sym(g_xlh2);
    float* xr2  = (float*)sym(g_xr2);
    float* acc1 = (float*)sym(g_acc1);
    float* acc2 = (float*)sym(g_acc2);
    int* deg    = (int*)sym(g_deg);
    int* off    = (int*)sym(g_off);
    int* cursor = (int*)sym(g_cursor);
    int* srcs   = (int*)sym(g_srcs);
    float* eas  = (float*)sym(g_eas);

    cudaFuncSetAttribute(gemm_f16_tile_k<8, 1>,
                         cudaFuncAttributeMaxDynamicSharedMemorySize, GEMM_SMEM);
    cudaFuncSetAttribute(gemm_f16_tile_k<2, 4>,
                         cudaFuncAttributeMaxDynamicSharedMemorySize, GEMM_SMEM);

    // 0-2: CSR histogram + scan
    zero_deg_k<<<(NN + 255) / 256, 256>>>(deg);
    hist_k<<<(NE + 255) / 256, 256>>>(dstp, deg);
    scan_k<<<1, 1024>>>(deg, off, cursor);

    // 3: layer 1 transforms (profiler capture slot)
    dim3 g1(2, (NN + 127) / 128);
    gemm_f16_tile_k<8, 1><<<g1, 256, GEMM_SMEM>>>(x, Wl1, Wr1, bl1, br1, xlh1, xr1, NN, D1, D2);

    // 4: permute edges into CSR order
    scatter_k<<<(NE + 255) / 256, 256>>>(srcp, dstp, eattr, cursor, srcs, eas);

    // 5: CSR edge pass layer 1
    gat_edge1_k<<<(NN * H * 32 + 255) / 256, 256>>>(srcs, eas, off, xlh1, xr1, We1, att1, acc1);

    // 6: silu + rmsnorm
    postact_rms_k<<<NN, 256>>>(acc1, bias1, w_ln1, acc1, D1, 1);

    // 7: layer 2 transforms
    dim3 g2(2, (NN + 127) / 128);
    gemm_f16_tile_k<2, 4><<<g2, 256, GEMM_SMEM>>>(acc1, Wl2, Wr2, bl2, br2, xlh2, xr2, NN, D2, D1);

    // 8: CSR edge pass layer 2
    gat_edge2_k<<<(NN * 32 + 255) / 256, 256>>>(srcs, eas, off, xlh2, xr2, We2, att2, acc2);

    // 9: rmsnorm
    postact_rms_k<<<NN, 128>>>(acc2, bias2, w_ln3, acc2, D2, 0);

    // 10: classifier — warp per node
    out_gemm_k<<<(NN + 7) / 8, 256>>>(acc2, W_out, out);
}